// round 1
// baseline (speedup 1.0000x reference)
#include <cuda_runtime.h>

#define HID   4096
#define NH    32
#define NKV   8
#define HD    128
#define BATCH 4
#define SEQ   1024
#define MROWS (BATCH*SEQ)   // 4096

// Scratch (static __device__ — no allocations allowed)
__device__ float g_q[(size_t)BATCH*NH*SEQ*HD];    // (b,h,t,d)
__device__ float g_k[(size_t)BATCH*NKV*SEQ*HD];   // (b,kvh,t,d)
__device__ float g_v[(size_t)BATCH*NKV*SEQ*HD];
__device__ float g_o[(size_t)MROWS*HID];          // (b,t, h*128+d)

// ---------------------------------------------------------------------------
// C[M,N] = A[M,K] * B[N,K]^T   (A row-major, B = weight [N,K] row-major)
// 128x128 tile, BK=16, 256 threads, 8x8 per thread.
// MODE 0: plain C[m*N+n]; MODE 1: scatter to (b,h,t,d) 32 heads;
// MODE 2: scatter to (b,kvh,t,d) 8 heads.
// ---------------------------------------------------------------------------
template<int MODE>
__global__ __launch_bounds__(256)
void gemm_nt(const float* __restrict__ A, const float* __restrict__ Bw,
             float* __restrict__ C, int N, int K)
{
    __shared__ float As[16*132];
    __shared__ float Bs[16*132];
    const int tid = threadIdx.x;
    const int tx  = tid & 15;
    const int ty  = tid >> 4;
    const int mBase = blockIdx.y << 7;
    const int nBase = blockIdx.x << 7;
    const float* Ab = A  + (size_t)mBase * K;
    const float* Bb = Bw + (size_t)nBase * K;

    float acc[8][8];
#pragma unroll
    for (int i = 0; i < 8; i++)
#pragma unroll
        for (int j = 0; j < 8; j++) acc[i][j] = 0.f;

    for (int k0 = 0; k0 < K; k0 += 16) {
#pragma unroll
        for (int it = 0; it < 2; it++) {
            int f   = tid + (it << 8);      // 0..511 float4 slots
            int row = f >> 2;               // 0..127
            int kq  = (f & 3) << 2;         // 0,4,8,12
            float4 va = *(const float4*)(Ab + (size_t)row * K + k0 + kq);
            As[(kq+0)*132+row] = va.x;
            As[(kq+1)*132+row] = va.y;
            As[(kq+2)*132+row] = va.z;
            As[(kq+3)*132+row] = va.w;
            float4 vb = *(const float4*)(Bb + (size_t)row * K + k0 + kq);
            Bs[(kq+0)*132+row] = vb.x;
            Bs[(kq+1)*132+row] = vb.y;
            Bs[(kq+2)*132+row] = vb.z;
            Bs[(kq+3)*132+row] = vb.w;
        }
        __syncthreads();
#pragma unroll
        for (int kk = 0; kk < 16; kk++) {
            float4 a0 = *(const float4*)&As[kk*132 + ty*8];
            float4 a1 = *(const float4*)&As[kk*132 + ty*8 + 4];
            float4 b0 = *(const float4*)&Bs[kk*132 + tx*8];
            float4 b1 = *(const float4*)&Bs[kk*132 + tx*8 + 4];
            float a[8] = {a0.x,a0.y,a0.z,a0.w,a1.x,a1.y,a1.z,a1.w};
            float b[8] = {b0.x,b0.y,b0.z,b0.w,b1.x,b1.y,b1.z,b1.w};
#pragma unroll
            for (int i = 0; i < 8; i++)
#pragma unroll
                for (int j = 0; j < 8; j++)
                    acc[i][j] = fmaf(a[i], b[j], acc[i][j]);
        }
        __syncthreads();
    }

#pragma unroll
    for (int i = 0; i < 8; i++) {
        int m  = mBase + ty*8 + i;
        int bb = m >> 10;          // batch
        int t  = m & 1023;         // token
#pragma unroll
        for (int j = 0; j < 8; j += 4) {
            int n = nBase + tx*8 + j;
            float4 v = make_float4(acc[i][j], acc[i][j+1], acc[i][j+2], acc[i][j+3]);
            if (MODE == 0) {
                *(float4*)&C[(size_t)m * N + n] = v;
            } else if (MODE == 1) {
                int h = n >> 7, d = n & 127;
                *(float4*)&C[(((size_t)(bb*NH  + h))*SEQ + t)*HD + d] = v;
            } else {
                int h = n >> 7, d = n & 127;
                *(float4*)&C[(((size_t)(bb*NKV + h))*SEQ + t)*HD + d] = v;
            }
        }
    }
}

// ---------------------------------------------------------------------------
// Fused flash-style attention. One block: 32 q-rows of one (b,h).
// Key tiles of 64, online softmax.  Mask: kpos <= qpos+1  AND  id[kpos]!=0.
// kv head = h % 8 (reference's broadcast/reshape semantics).
// ---------------------------------------------------------------------------
__global__ __launch_bounds__(256)
void attn_kernel(const int* __restrict__ ids, float* __restrict__ O)
{
    extern __shared__ float smf[];
    float* Qs   = smf;                 // 32*128
    float* Ks   = Qs + 32*128;         // 64*128
    float* Vs   = Ks + 64*128;         // 64*128
    float* Sm   = Vs + 64*128;         // 32*64
    float* Kval = Sm + 32*64;          // 64

    const int q0  = blockIdx.x << 5;
    const int h   = blockIdx.y;
    const int b   = blockIdx.z;
    const int kvh = h & 7;
    const int tid = threadIdx.x;

    const float* Qg = g_q + ((size_t)(b*NH  + h  ))*SEQ*HD;
    const float* Kg = g_k + ((size_t)(b*NKV + kvh))*SEQ*HD;
    const float* Vg = g_v + ((size_t)(b*NKV + kvh))*SEQ*HD;

    // load Q tile (32x128)
#pragma unroll
    for (int it = 0; it < 4; it++) {
        int f   = tid + (it << 8);
        int row = f >> 5;
        int c   = (f & 31) << 2;
        *(float4*)&Qs[row*128 + c] = *(const float4*)&Qg[(size_t)(q0+row)*HD + c];
    }

    const int r    = tid >> 3;     // q-row within tile, 0..31
    const int g    = tid & 7;      // group lane
    const int qpos = q0 + r;
    const int cb   = g << 2;       // this thread's col base: cb, cb+32, cb+64, cb+96

    float mrun = -1e30f, lrun = 0.f;
    float4 acc0 = make_float4(0,0,0,0), acc1 = acc0, acc2 = acc0, acc3 = acc0;

    const int kmax = q0 + 32;      // largest key any row in tile can see (q+1)
    for (int k0 = 0; k0 <= kmax && k0 < SEQ; k0 += 64) {
        __syncthreads();  // previous tile fully consumed (also covers Q load)
#pragma unroll
        for (int it = 0; it < 8; it++) {
            int f   = tid + (it << 8);
            int row = f >> 5;
            int c   = (f & 31) << 2;
            *(float4*)&Ks[row*128 + c] = *(const float4*)&Kg[(size_t)(k0+row)*HD + c];
            *(float4*)&Vs[row*128 + c] = *(const float4*)&Vg[(size_t)(k0+row)*HD + c];
        }
        if (tid < 64) Kval[tid] = (ids[b*SEQ + k0 + tid] != 0) ? 1.0f : 0.0f;
        __syncthreads();

        // S tile: thread computes row r, cols g*8 .. g*8+7
        float s[8];
#pragma unroll
        for (int jj = 0; jj < 8; jj++) s[jj] = 0.f;
#pragma unroll 4
        for (int d = 0; d < 128; d += 4) {
            float4 qv = *(const float4*)&Qs[r*128 + d];
#pragma unroll
            for (int jj = 0; jj < 8; jj++) {
                float4 kv = *(const float4*)&Ks[(g*8+jj)*128 + d];
                s[jj] += qv.x*kv.x + qv.y*kv.y + qv.z*kv.z + qv.w*kv.w;
            }
        }
        float tmax = -1e30f;
#pragma unroll
        for (int jj = 0; jj < 8; jj++) {
            int kpos = k0 + g*8 + jj;
            float sv = s[jj] * 0.08838834764831845f;   // 1/sqrt(128)
            if (kpos > qpos + 1 || Kval[g*8+jj] == 0.0f) sv = -1e30f;
            s[jj] = sv;
            tmax = fmaxf(tmax, sv);
        }
        tmax = fmaxf(tmax, __shfl_xor_sync(0xffffffffu, tmax, 1, 8));
        tmax = fmaxf(tmax, __shfl_xor_sync(0xffffffffu, tmax, 2, 8));
        tmax = fmaxf(tmax, __shfl_xor_sync(0xffffffffu, tmax, 4, 8));
        float mnew  = fmaxf(mrun, tmax);
        float scale = __expf(mrun - mnew);
        float psum  = 0.f;
#pragma unroll
        for (int jj = 0; jj < 8; jj++) {
            float p = (s[jj] <= -1e29f) ? 0.f : __expf(s[jj] - mnew);
            s[jj] = p;
            psum += p;
        }
        psum += __shfl_xor_sync(0xffffffffu, psum, 1, 8);
        psum += __shfl_xor_sync(0xffffffffu, psum, 2, 8);
        psum += __shfl_xor_sync(0xffffffffu, psum, 4, 8);
        lrun = lrun * scale + psum;
        mrun = mnew;
        acc0.x*=scale; acc0.y*=scale; acc0.z*=scale; acc0.w*=scale;
        acc1.x*=scale; acc1.y*=scale; acc1.z*=scale; acc1.w*=scale;
        acc2.x*=scale; acc2.y*=scale; acc2.z*=scale; acc2.w*=scale;
        acc3.x*=scale; acc3.y*=scale; acc3.z*=scale; acc3.w*=scale;
#pragma unroll
        for (int jj = 0; jj < 8; jj++) Sm[r*64 + g*8 + jj] = s[jj];
        __syncthreads();

        // acc += P @ V
#pragma unroll 4
        for (int j = 0; j < 64; j++) {
            float p = Sm[r*64 + j];
            const float* vrow = &Vs[j*128 + cb];
            float4 v0 = *(const float4*)(vrow);
            float4 v1 = *(const float4*)(vrow + 32);
            float4 v2 = *(const float4*)(vrow + 64);
            float4 v3 = *(const float4*)(vrow + 96);
            acc0.x = fmaf(p, v0.x, acc0.x); acc0.y = fmaf(p, v0.y, acc0.y);
            acc0.z = fmaf(p, v0.z, acc0.z); acc0.w = fmaf(p, v0.w, acc0.w);
            acc1.x = fmaf(p, v1.x, acc1.x); acc1.y = fmaf(p, v1.y, acc1.y);
            acc1.z = fmaf(p, v1.z, acc1.z); acc1.w = fmaf(p, v1.w, acc1.w);
            acc2.x = fmaf(p, v2.x, acc2.x); acc2.y = fmaf(p, v2.y, acc2.y);
            acc2.z = fmaf(p, v2.z, acc2.z); acc2.w = fmaf(p, v2.w, acc2.w);
            acc3.x = fmaf(p, v3.x, acc3.x); acc3.y = fmaf(p, v3.y, acc3.y);
            acc3.z = fmaf(p, v3.z, acc3.z); acc3.w = fmaf(p, v3.w, acc3.w);
        }
    }

    float inv = 1.0f / lrun;
    float* Og = O + ((size_t)(b*SEQ + qpos))*HID + h*HD;
    float4 o;
    o = make_float4(acc0.x*inv, acc0.y*inv, acc0.z*inv, acc0.w*inv); *(float4*)&Og[cb     ] = o;
    o = make_float4(acc1.x*inv, acc1.y*inv, acc1.z*inv, acc1.w*inv); *(float4*)&Og[cb + 32] = o;
    o = make_float4(acc2.x*inv, acc2.y*inv, acc2.z*inv, acc2.w*inv); *(float4*)&Og[cb + 64] = o;
    o = make_float4(acc3.x*inv, acc3.y*inv, acc3.z*inv, acc3.w*inv); *(float4*)&Og[cb + 96] = o;
}

// Tail: reference returns (out, start_pos + Tq) — fill any extra output slots.
__global__ void tail_kernel(float* __restrict__ out, const int* __restrict__ sp, int out_size)
{
    int i = MROWS*HID + blockIdx.x*blockDim.x + threadIdx.x;
    if (i < out_size) {
        int s = sp ? *sp : 0;
        out[i] = (float)(s + SEQ);
    }
}

extern "C" void kernel_launch(void* const* d_in, const int* in_sizes, int n_in,
                              void* d_out, int out_size)
{
    const int*   ids    = (const int*)  d_in[0];
    const float* hidden = (const float*)d_in[1];
    const float* Wq     = (const float*)d_in[2];
    const float* Wk     = (const float*)d_in[3];
    const float* Wv     = (const float*)d_in[4];
    const float* Wo     = (const float*)d_in[5];
    float*       out    = (float*)d_out;

    float *qb, *kb, *vb, *ob;
    cudaGetSymbolAddress((void**)&qb, g_q);
    cudaGetSymbolAddress((void**)&kb, g_k);
    cudaGetSymbolAddress((void**)&vb, g_v);
    cudaGetSymbolAddress((void**)&ob, g_o);

    dim3 blk(256);
    gemm_nt<1><<<dim3(HID/128,      MROWS/128), blk>>>(hidden, Wq, qb, HID,    HID);
    gemm_nt<2><<<dim3((NKV*HD)/128, MROWS/128), blk>>>(hidden, Wk, kb, NKV*HD, HID);
    gemm_nt<2><<<dim3((NKV*HD)/128, MROWS/128), blk>>>(hidden, Wv, vb, NKV*HD, HID);

    const size_t smem = (size_t)(32*128 + 2*64*128 + 32*64 + 64) * sizeof(float); // 90368 B
    cudaFuncSetAttribute(attn_kernel, cudaFuncAttributeMaxDynamicSharedMemorySize, (int)smem);
    attn_kernel<<<dim3(SEQ/32, NH, BATCH), blk, smem>>>(ids, ob);

    gemm_nt<0><<<dim3(HID/128, MROWS/128), blk>>>(ob, Wo, out, HID, HID);

    if (out_size > MROWS*HID) {
        int rem = out_size - MROWS*HID;
        const int* sp = (n_in > 8) ? (const int*)d_in[8] : nullptr;
        tail_kernel<<<(rem + 127)/128, 128>>>(out, sp, out_size);
    }
}

// round 2
// speedup vs baseline: 1.3407x; 1.3407x over previous
#include <cuda_runtime.h>
#include <cstdint>

#define HID   4096
#define NH    32
#define NKV   8
#define HD    128
#define BATCH 4
#define SEQ   1024
#define MROWS (BATCH*SEQ)   // 4096

// Scratch (static __device__ — no allocations allowed)
__device__ float g_q[(size_t)BATCH*NH*SEQ*HD];    // (b,h,t,d)
__device__ float g_k[(size_t)BATCH*NKV*SEQ*HD];   // (b,kvh,t,d)
__device__ float g_v[(size_t)BATCH*NKV*SEQ*HD];
__device__ float g_o[(size_t)MROWS*HID];          // (b,t, h*128+d)

// ---------------------------------------------------------------------------
// helpers
// ---------------------------------------------------------------------------
__device__ __forceinline__ uint32_t f2tf(float x) {
    uint32_t u;
    asm("cvt.rna.tf32.f32 %0, %1;" : "=r"(u) : "f"(x));
    return u;
}
__device__ __forceinline__ void cpasync16(void* smem, const void* gmem) {
    uint32_t s = (uint32_t)__cvta_generic_to_shared(smem);
    asm volatile("cp.async.cg.shared.global [%0], [%1], 16;" :: "r"(s), "l"(gmem));
}
#define CP_COMMIT() asm volatile("cp.async.commit_group;")
#define CP_WAIT(n)  asm volatile("cp.async.wait_group %0;" :: "n"(n))

#define MMA_TF32(d, a0,a1,a2,a3, b0,b1)                                   \
    asm volatile("mma.sync.aligned.m16n8k8.row.col.f32.tf32.tf32.f32 "    \
        "{%0,%1,%2,%3}, {%4,%5,%6,%7}, {%8,%9}, {%0,%1,%2,%3};"           \
        : "+f"(d[0]), "+f"(d[1]), "+f"(d[2]), "+f"(d[3])                  \
        : "r"(a0), "r"(a1), "r"(a2), "r"(a3), "r"(b0), "r"(b1))

// ---------------------------------------------------------------------------
// Tensor-core TF32 GEMM:  C[M,N] = A[M,K] * B[N,K]^T
// 128x128 tile, BK=16, 3-stage cp.async pipeline, 256 threads (8 warps 2x4),
// warp tile 64x32, m16n8k8 tf32 mma.
// k-permutation: mma-chunk0 uses logical k = {4t,4t+1}, chunk1 = {4t+2,4t+3}
// so each fragment is ONE lds.128 from plain row-major smem (conflict-free).
// MODE 0: C[m*N+n];  MODE 1: scatter to (b,h,t,d) 32 heads;
// MODE 2: scatter to (b,kvh,t,d) 8 heads.
// ---------------------------------------------------------------------------
template<int MODE>
__global__ __launch_bounds__(256, 1)
void gemm_tf32(const float* __restrict__ A, const float* __restrict__ Bw,
               float* __restrict__ C, int N, int K)
{
    constexpr int BM = 128, BN = 128, BK = 16, STG = 3;
    __shared__ float As[STG][BM][BK];   // 24 KB
    __shared__ float Bs[STG][BN][BK];   // 24 KB

    const int tid  = threadIdx.x;
    const int w    = tid >> 5;
    const int lane = tid & 31;
    const int g    = lane >> 2;     // 0..7
    const int t    = lane & 3;      // 0..3
    const int wm   = (w & 1) * 64;  // warp row offset
    const int wn   = (w >> 1) * 32; // warp col offset
    const int mBase = blockIdx.y * BM;
    const int nBase = blockIdx.x * BN;

    const float* Ag = A  + (size_t)mBase * K;
    const float* Bg = Bw + (size_t)nBase * K;

    // global->smem: thread covers rows lr, lr+64 (cols lk..lk+3) for A and B
    const int lr = tid >> 2;          // 0..63
    const int lk = (tid & 3) << 2;    // 0,4,8,12

    float acc[4][4][4];
#pragma unroll
    for (int i = 0; i < 4; i++)
#pragma unroll
        for (int j = 0; j < 4; j++)
#pragma unroll
            for (int r = 0; r < 4; r++) acc[i][j][r] = 0.f;

    const int kTiles = K / BK;

    auto issue = [&](int stage, int kt) {
        int k0 = kt * BK;
        cpasync16(&As[stage][lr     ][lk], Ag + (size_t)(lr     ) * K + k0 + lk);
        cpasync16(&As[stage][lr + 64][lk], Ag + (size_t)(lr + 64) * K + k0 + lk);
        cpasync16(&Bs[stage][lr     ][lk], Bg + (size_t)(lr     ) * K + k0 + lk);
        cpasync16(&Bs[stage][lr + 64][lk], Bg + (size_t)(lr + 64) * K + k0 + lk);
    };

#pragma unroll
    for (int s = 0; s < STG - 1; s++) { issue(s, s); CP_COMMIT(); }

    for (int kt = 0; kt < kTiles; kt++) {
        CP_WAIT(STG - 2);
        __syncthreads();

        // prefetch tile kt+STG-1 into stage (kt-1)%STG (finished last iter)
        int nft = kt + STG - 1;
        if (nft < kTiles) issue(nft % STG, nft);
        CP_COMMIT();

        const int c = kt % STG;
        uint32_t af[4][8], bf[4][4];
#pragma unroll
        for (int mt = 0; mt < 4; mt++) {
            float4 v0 = *(const float4*)&As[c][wm + mt*16 + g    ][4*t];
            float4 v1 = *(const float4*)&As[c][wm + mt*16 + g + 8][4*t];
            // chunk0: a0=v0.x a1=v1.x a2=v0.y a3=v1.y ; chunk1: .z/.w
            af[mt][0] = f2tf(v0.x); af[mt][1] = f2tf(v1.x);
            af[mt][2] = f2tf(v0.y); af[mt][3] = f2tf(v1.y);
            af[mt][4] = f2tf(v0.z); af[mt][5] = f2tf(v1.z);
            af[mt][6] = f2tf(v0.w); af[mt][7] = f2tf(v1.w);
        }
#pragma unroll
        for (int nt = 0; nt < 4; nt++) {
            float4 vb = *(const float4*)&Bs[c][wn + nt*8 + g][4*t];
            bf[nt][0] = f2tf(vb.x); bf[nt][1] = f2tf(vb.y);
            bf[nt][2] = f2tf(vb.z); bf[nt][3] = f2tf(vb.w);
        }
#pragma unroll
        for (int mt = 0; mt < 4; mt++)
#pragma unroll
            for (int nt = 0; nt < 4; nt++) {
                MMA_TF32(acc[mt][nt], af[mt][0], af[mt][1], af[mt][2], af[mt][3],
                         bf[nt][0], bf[nt][1]);
                MMA_TF32(acc[mt][nt], af[mt][4], af[mt][5], af[mt][6], af[mt][7],
                         bf[nt][2], bf[nt][3]);
            }
        __syncthreads();
    }

    // epilogue: c0,c1 -> (row g, cols 2t,2t+1); c2,c3 -> (row g+8)
#pragma unroll
    for (int mt = 0; mt < 4; mt++) {
#pragma unroll
        for (int nt = 0; nt < 4; nt++) {
            int m = mBase + wm + mt*16 + g;
            int n = nBase + wn + nt*8 + 2*t;
#pragma unroll
            for (int half = 0; half < 2; half++) {
                int mm = m + half*8;
                float2 v = half ? make_float2(acc[mt][nt][2], acc[mt][nt][3])
                                : make_float2(acc[mt][nt][0], acc[mt][nt][1]);
                if (MODE == 0) {
                    *(float2*)&C[(size_t)mm * N + n] = v;
                } else {
                    int bb = mm >> 10, tk = mm & 1023;
                    int h = n >> 7, d = n & 127;
                    int heads = (MODE == 1) ? NH : NKV;
                    *(float2*)&C[(((size_t)(bb*heads + h))*SEQ + tk)*HD + d] = v;
                }
            }
        }
    }
}

// ---------------------------------------------------------------------------
// Fused flash-style attention (fp32 SIMT — attention is ~10us, not the
// bottleneck). Mask: kpos <= qpos+1 AND id[kpos]!=0;  kv head = h % 8.
// ---------------------------------------------------------------------------
__global__ __launch_bounds__(256)
void attn_kernel(const int* __restrict__ ids, float* __restrict__ O)
{
    extern __shared__ float smf[];
    float* Qs   = smf;                 // 32*128
    float* Ks   = Qs + 32*128;         // 64*128
    float* Vs   = Ks + 64*128;         // 64*128
    float* Sm   = Vs + 64*128;         // 32*64
    float* Kval = Sm + 32*64;          // 64

    const int q0  = blockIdx.x << 5;
    const int h   = blockIdx.y;
    const int b   = blockIdx.z;
    const int kvh = h & 7;
    const int tid = threadIdx.x;

    const float* Qg = g_q + ((size_t)(b*NH  + h  ))*SEQ*HD;
    const float* Kg = g_k + ((size_t)(b*NKV + kvh))*SEQ*HD;
    const float* Vg = g_v + ((size_t)(b*NKV + kvh))*SEQ*HD;

#pragma unroll
    for (int it = 0; it < 4; it++) {
        int f   = tid + (it << 8);
        int row = f >> 5;
        int c   = (f & 31) << 2;
        *(float4*)&Qs[row*128 + c] = *(const float4*)&Qg[(size_t)(q0+row)*HD + c];
    }

    const int r    = tid >> 3;
    const int g    = tid & 7;
    const int qpos = q0 + r;
    const int cb   = g << 2;

    float mrun = -1e30f, lrun = 0.f;
    float4 acc0 = make_float4(0,0,0,0), acc1 = acc0, acc2 = acc0, acc3 = acc0;

    const int kmax = q0 + 32;
    for (int k0 = 0; k0 <= kmax && k0 < SEQ; k0 += 64) {
        __syncthreads();
#pragma unroll
        for (int it = 0; it < 8; it++) {
            int f   = tid + (it << 8);
            int row = f >> 5;
            int c   = (f & 31) << 2;
            *(float4*)&Ks[row*128 + c] = *(const float4*)&Kg[(size_t)(k0+row)*HD + c];
            *(float4*)&Vs[row*128 + c] = *(const float4*)&Vg[(size_t)(k0+row)*HD + c];
        }
        if (tid < 64) Kval[tid] = (ids[b*SEQ + k0 + tid] != 0) ? 1.0f : 0.0f;
        __syncthreads();

        float s[8];
#pragma unroll
        for (int jj = 0; jj < 8; jj++) s[jj] = 0.f;
#pragma unroll 4
        for (int d = 0; d < 128; d += 4) {
            float4 qv = *(const float4*)&Qs[r*128 + d];
#pragma unroll
            for (int jj = 0; jj < 8; jj++) {
                float4 kv = *(const float4*)&Ks[(g*8+jj)*128 + d];
                s[jj] += qv.x*kv.x + qv.y*kv.y + qv.z*kv.z + qv.w*kv.w;
            }
        }
        float tmax = -1e30f;
#pragma unroll
        for (int jj = 0; jj < 8; jj++) {
            int kpos = k0 + g*8 + jj;
            float sv = s[jj] * 0.08838834764831845f;
            if (kpos > qpos + 1 || Kval[g*8+jj] == 0.0f) sv = -1e30f;
            s[jj] = sv;
            tmax = fmaxf(tmax, sv);
        }
        tmax = fmaxf(tmax, __shfl_xor_sync(0xffffffffu, tmax, 1, 8));
        tmax = fmaxf(tmax, __shfl_xor_sync(0xffffffffu, tmax, 2, 8));
        tmax = fmaxf(tmax, __shfl_xor_sync(0xffffffffu, tmax, 4, 8));
        float mnew  = fmaxf(mrun, tmax);
        float scale = __expf(mrun - mnew);
        float psum  = 0.f;
#pragma unroll
        for (int jj = 0; jj < 8; jj++) {
            float p = (s[jj] <= -1e29f) ? 0.f : __expf(s[jj] - mnew);
            s[jj] = p;
            psum += p;
        }
        psum += __shfl_xor_sync(0xffffffffu, psum, 1, 8);
        psum += __shfl_xor_sync(0xffffffffu, psum, 2, 8);
        psum += __shfl_xor_sync(0xffffffffu, psum, 4, 8);
        lrun = lrun * scale + psum;
        mrun = mnew;
        acc0.x*=scale; acc0.y*=scale; acc0.z*=scale; acc0.w*=scale;
        acc1.x*=scale; acc1.y*=scale; acc1.z*=scale; acc1.w*=scale;
        acc2.x*=scale; acc2.y*=scale; acc2.z*=scale; acc2.w*=scale;
        acc3.x*=scale; acc3.y*=scale; acc3.z*=scale; acc3.w*=scale;
#pragma unroll
        for (int jj = 0; jj < 8; jj++) Sm[r*64 + g*8 + jj] = s[jj];
        __syncthreads();

#pragma unroll 4
        for (int j = 0; j < 64; j++) {
            float p = Sm[r*64 + j];
            const float* vrow = &Vs[j*128 + cb];
            float4 v0 = *(const float4*)(vrow);
            float4 v1 = *(const float4*)(vrow + 32);
            float4 v2 = *(const float4*)(vrow + 64);
            float4 v3 = *(const float4*)(vrow + 96);
            acc0.x = fmaf(p, v0.x, acc0.x); acc0.y = fmaf(p, v0.y, acc0.y);
            acc0.z = fmaf(p, v0.z, acc0.z); acc0.w = fmaf(p, v0.w, acc0.w);
            acc1.x = fmaf(p, v1.x, acc1.x); acc1.y = fmaf(p, v1.y, acc1.y);
            acc1.z = fmaf(p, v1.z, acc1.z); acc1.w = fmaf(p, v1.w, acc1.w);
            acc2.x = fmaf(p, v2.x, acc2.x); acc2.y = fmaf(p, v2.y, acc2.y);
            acc2.z = fmaf(p, v2.z, acc2.z); acc2.w = fmaf(p, v2.w, acc2.w);
            acc3.x = fmaf(p, v3.x, acc3.x); acc3.y = fmaf(p, v3.y, acc3.y);
            acc3.z = fmaf(p, v3.z, acc3.z); acc3.w = fmaf(p, v3.w, acc3.w);
        }
    }

    float inv = 1.0f / lrun;
    float* Og = O + ((size_t)(b*SEQ + qpos))*HID + h*HD;
    float4 o;
    o = make_float4(acc0.x*inv, acc0.y*inv, acc0.z*inv, acc0.w*inv); *(float4*)&Og[cb     ] = o;
    o = make_float4(acc1.x*inv, acc1.y*inv, acc1.z*inv, acc1.w*inv); *(float4*)&Og[cb + 32] = o;
    o = make_float4(acc2.x*inv, acc2.y*inv, acc2.z*inv, acc2.w*inv); *(float4*)&Og[cb + 64] = o;
    o = make_float4(acc3.x*inv, acc3.y*inv, acc3.z*inv, acc3.w*inv); *(float4*)&Og[cb + 96] = o;
}

// Tail: reference returns (out, start_pos + Tq) — fill any extra output slots.
__global__ void tail_kernel(float* __restrict__ out, const int* __restrict__ sp, int out_size)
{
    int i = MROWS*HID + blockIdx.x*blockDim.x + threadIdx.x;
    if (i < out_size) {
        int s = sp ? *sp : 0;
        out[i] = (float)(s + SEQ);
    }
}

extern "C" void kernel_launch(void* const* d_in, const int* in_sizes, int n_in,
                              void* d_out, int out_size)
{
    const int*   ids    = (const int*)  d_in[0];
    const float* hidden = (const float*)d_in[1];
    const float* Wq     = (const float*)d_in[2];
    const float* Wk     = (const float*)d_in[3];
    const float* Wv     = (const float*)d_in[4];
    const float* Wo     = (const float*)d_in[5];
    float*       out    = (float*)d_out;

    float *qb, *kb, *vb, *ob;
    cudaGetSymbolAddress((void**)&qb, g_q);
    cudaGetSymbolAddress((void**)&kb, g_k);
    cudaGetSymbolAddress((void**)&vb, g_v);
    cudaGetSymbolAddress((void**)&ob, g_o);

    dim3 blk(256);
    gemm_tf32<1><<<dim3(HID/128,      MROWS/128), blk>>>(hidden, Wq, qb, HID,    HID);
    gemm_tf32<2><<<dim3((NKV*HD)/128, MROWS/128), blk>>>(hidden, Wk, kb, NKV*HD, HID);
    gemm_tf32<2><<<dim3((NKV*HD)/128, MROWS/128), blk>>>(hidden, Wv, vb, NKV*HD, HID);

    const size_t smem = (size_t)(32*128 + 2*64*128 + 32*64 + 64) * sizeof(float); // 90368 B
    cudaFuncSetAttribute(attn_kernel, cudaFuncAttributeMaxDynamicSharedMemorySize, (int)smem);
    attn_kernel<<<dim3(SEQ/32, NH, BATCH), blk, smem>>>(ids, ob);

    gemm_tf32<0><<<dim3(HID/128, MROWS/128), blk>>>(ob, Wo, out, HID, HID);

    if (out_size > MROWS*HID) {
        int rem = out_size - MROWS*HID;
        const int* sp = (n_in > 8) ? (const int*)d_in[8] : nullptr;
        tail_kernel<<<(rem + 127)/128, 128>>>(out, sp, out_size);
    }
}

// round 4
// speedup vs baseline: 1.4157x; 1.0559x over previous
#include <cuda_runtime.h>
#include <cstdint>

#define HID   4096
#define NH    32
#define NKV   8
#define HD    128
#define BATCH 4
#define SEQ   1024
#define MROWS (BATCH*SEQ)   // 4096

// ---------------------------------------------------------------------------
// Scratch (static __device__ — no allocations allowed)
// ---------------------------------------------------------------------------
__device__ float g_q [(size_t)BATCH*NH *SEQ*HD];   // (b,h,t,d)
__device__ float g_k [(size_t)BATCH*NKV*SEQ*HD];   // (b,kvh,t,d)
__device__ float g_v [(size_t)BATCH*NKV*SEQ*HD];
__device__ float g_o [(size_t)MROWS*HID];          // attention out
// tf32-rounded operand copies
__device__ float g_hr [(size_t)MROWS*HID];
__device__ float g_or [(size_t)MROWS*HID];
__device__ float g_wqr[(size_t)HID*HID];
__device__ float g_wkr[(size_t)NKV*HD*HID];
__device__ float g_wvr[(size_t)NKV*HD*HID];
__device__ float g_wor[(size_t)HID*HID];

// ---------------------------------------------------------------------------
__device__ __forceinline__ uint32_t f2tf(float x) {
    uint32_t u; asm("cvt.rna.tf32.f32 %0, %1;" : "=r"(u) : "f"(x)); return u;
}
__device__ __forceinline__ void cpasync16(void* smem, const void* gmem) {
    uint32_t s = (uint32_t)__cvta_generic_to_shared(smem);
    asm volatile("cp.async.cg.shared.global [%0], [%1], 16;" :: "r"(s), "l"(gmem));
}
#define CP_COMMIT() asm volatile("cp.async.commit_group;")
#define CP_WAIT(n)  asm volatile("cp.async.wait_group %0;" :: "n"(n))

#define MMA_TF32(d, a0,a1,a2,a3, b0,b1)                                   \
    asm volatile("mma.sync.aligned.m16n8k8.row.col.f32.tf32.tf32.f32 "    \
        "{%0,%1,%2,%3}, {%4,%5,%6,%7}, {%8,%9}, {%0,%1,%2,%3};"           \
        : "+f"(d[0]), "+f"(d[1]), "+f"(d[2]), "+f"(d[3])                  \
        : "r"(a0), "r"(a1), "r"(a2), "r"(a3), "r"(b0), "r"(b1))

// ---------------------------------------------------------------------------
// TF32 mma.sync GEMM, NO in-loop cvt (operands pre-rounded to tf32 bits).
// C[M,N] = A[M,K] * B[N,K]^T.  128x128 CTA tile, BK=32 (2 x K16 sub-buffers,
// 64B row stride -> conflict-free lds.128), 4-stage cp.async, 256 threads
// (8 warps, warp tile 64x32), m16n8k8.
// MODE 0: C[m*N+n]; MODE 1: scatter (b,h,t,d) 32 heads; MODE 2: 8 heads.
// ---------------------------------------------------------------------------
#define STG 4
#define BKC 32
// per array: STG*2*128*16 floats = 16384 floats = 64KB; A+B = 128KB
#define GEMM_SMEM (STG*2*128*16*4*2)

template<int MODE>
__global__ __launch_bounds__(256, 1)
void gemm_tf32(const float* __restrict__ A, const float* __restrict__ Bw,
               float* __restrict__ C, int N, int K)
{
    extern __shared__ float sm[];
    float* As = sm;                        // [STG][2][128][16]
    float* Bs = sm + STG*2*128*16;

    const int tid  = threadIdx.x;
    const int w    = tid >> 5;
    const int lane = tid & 31;
    const int g    = lane >> 2;     // 0..7
    const int t    = lane & 3;      // 0..3
    const int wm   = (w & 1) * 64;
    const int wn   = (w >> 1) * 32;
    const int mBase = blockIdx.y << 7;
    const int nBase = blockIdx.x << 7;
    const float* Ag = A  + (size_t)mBase * K;
    const float* Bg = Bw + (size_t)nBase * K;

    float acc[4][4][4];
#pragma unroll
    for (int i = 0; i < 4; i++)
#pragma unroll
        for (int j = 0; j < 4; j++)
#pragma unroll
            for (int r = 0; r < 4; r++) acc[i][j][r] = 0.f;

    // cp.async: 1024 16B slots per array; thread covers 4 each.
    auto issue = [&](int kt) {
        const int st = kt & (STG - 1);
        const int k0 = kt * BKC;
#pragma unroll
        for (int i = 0; i < 4; i++) {
            int slot = tid + (i << 8);
            int r = slot >> 3;          // row 0..127
            int c = slot & 7;           // 16B chunk (4 k-cols)
            int idx = (((st*2 + (c >> 2)) * 128 + r) * 16) + (c & 3) * 4;
            cpasync16(&As[idx], Ag + (size_t)r * K + k0 + c*4);
            cpasync16(&Bs[idx], Bg + (size_t)r * K + k0 + c*4);
        }
    };

    const int kTiles = K / BKC;
#pragma unroll
    for (int s = 0; s < STG - 1; s++) { issue(s); CP_COMMIT(); }

    for (int kt = 0; kt < kTiles; kt++) {
        CP_WAIT(STG - 2);
        __syncthreads();

        int nft = kt + STG - 1;
        if (nft < kTiles) issue(nft);   // overwrites stage consumed at kt-1
        CP_COMMIT();

        const int st = kt & (STG - 1);
#pragma unroll
        for (int h = 0; h < 2; h++) {
            const float* Ah = &As[(st*2 + h) * 128 * 16];
            const float* Bh = &Bs[(st*2 + h) * 128 * 16];
            uint32_t af[4][8], bf[4][4];
#pragma unroll
            for (int mt = 0; mt < 4; mt++) {
                float4 v0 = *(const float4*)&Ah[(wm + mt*16 + g    )*16 + 4*t];
                float4 v1 = *(const float4*)&Ah[(wm + mt*16 + g + 8)*16 + 4*t];
                af[mt][0] = __float_as_uint(v0.x); af[mt][1] = __float_as_uint(v1.x);
                af[mt][2] = __float_as_uint(v0.y); af[mt][3] = __float_as_uint(v1.y);
                af[mt][4] = __float_as_uint(v0.z); af[mt][5] = __float_as_uint(v1.z);
                af[mt][6] = __float_as_uint(v0.w); af[mt][7] = __float_as_uint(v1.w);
            }
#pragma unroll
            for (int nt = 0; nt < 4; nt++) {
                float4 vb = *(const float4*)&Bh[(wn + nt*8 + g)*16 + 4*t];
                bf[nt][0] = __float_as_uint(vb.x); bf[nt][1] = __float_as_uint(vb.y);
                bf[nt][2] = __float_as_uint(vb.z); bf[nt][3] = __float_as_uint(vb.w);
            }
#pragma unroll
            for (int mt = 0; mt < 4; mt++)
#pragma unroll
                for (int nt = 0; nt < 4; nt++) {
                    MMA_TF32(acc[mt][nt], af[mt][0], af[mt][1], af[mt][2], af[mt][3],
                             bf[nt][0], bf[nt][1]);
                    MMA_TF32(acc[mt][nt], af[mt][4], af[mt][5], af[mt][6], af[mt][7],
                             bf[nt][2], bf[nt][3]);
                }
        }
    }

    // epilogue
#pragma unroll
    for (int mt = 0; mt < 4; mt++) {
#pragma unroll
        for (int nt = 0; nt < 4; nt++) {
            int m = mBase + wm + mt*16 + g;
            int n = nBase + wn + nt*8 + 2*t;
#pragma unroll
            for (int half = 0; half < 2; half++) {
                int mm = m + half*8;
                float2 v = half ? make_float2(acc[mt][nt][2], acc[mt][nt][3])
                                : make_float2(acc[mt][nt][0], acc[mt][nt][1]);
                if (MODE == 0) {
                    *(float2*)&C[(size_t)mm * N + n] = v;
                } else {
                    int bb = mm >> 10, tk = mm & 1023;
                    int h2 = n >> 7, d = n & 127;
                    int heads = (MODE == 1) ? NH : NKV;
                    *(float2*)&C[(((size_t)(bb*heads + h2))*SEQ + tk)*HD + d] = v;
                }
            }
        }
    }
}

// ---------------------------------------------------------------------------
// tf32-rna rounding pre-pass
// ---------------------------------------------------------------------------
__global__ void round_tf32_kernel(float* __restrict__ dst, const float* __restrict__ src, int n4)
{
    int i = blockIdx.x * blockDim.x + threadIdx.x;
    if (i < n4) {
        float4 v = ((const float4*)src)[i];
        v.x = __uint_as_float(f2tf(v.x));
        v.y = __uint_as_float(f2tf(v.y));
        v.z = __uint_as_float(f2tf(v.z));
        v.w = __uint_as_float(f2tf(v.w));
        ((float4*)dst)[i] = v;
    }
}

// ---------------------------------------------------------------------------
// Fused flash-style attention (fp32 SIMT, ~10us).
// Mask: kpos <= qpos+1 AND id[kpos]!=0; kv head = h % 8.
// ---------------------------------------------------------------------------
__global__ __launch_bounds__(256)
void attn_kernel(const int* __restrict__ ids, float* __restrict__ O)
{
    extern __shared__ float smf[];
    float* Qs   = smf;
    float* Ks   = Qs + 32*128;
    float* Vs   = Ks + 64*128;
    float* Sm   = Vs + 64*128;
    float* Kval = Sm + 32*64;

    const int q0  = blockIdx.x << 5;
    const int h   = blockIdx.y;
    const int b   = blockIdx.z;
    const int kvh = h & 7;
    const int tid = threadIdx.x;

    const float* Qg = g_q + ((size_t)(b*NH  + h  ))*SEQ*HD;
    const float* Kg = g_k + ((size_t)(b*NKV + kvh))*SEQ*HD;
    const float* Vg = g_v + ((size_t)(b*NKV + kvh))*SEQ*HD;

#pragma unroll
    for (int it = 0; it < 4; it++) {
        int f = tid + (it << 8);
        int row = f >> 5, c = (f & 31) << 2;
        *(float4*)&Qs[row*128 + c] = *(const float4*)&Qg[(size_t)(q0+row)*HD + c];
    }

    const int r = tid >> 3, g = tid & 7;
    const int qpos = q0 + r;
    const int cb = g << 2;

    float mrun = -1e30f, lrun = 0.f;
    float4 acc0 = make_float4(0,0,0,0), acc1 = acc0, acc2 = acc0, acc3 = acc0;

    const int kmax = q0 + 32;
    for (int k0 = 0; k0 <= kmax && k0 < SEQ; k0 += 64) {
        __syncthreads();
#pragma unroll
        for (int it = 0; it < 8; it++) {
            int f = tid + (it << 8);
            int row = f >> 5, c = (f & 31) << 2;
            *(float4*)&Ks[row*128 + c] = *(const float4*)&Kg[(size_t)(k0+row)*HD + c];
            *(float4*)&Vs[row*128 + c] = *(const float4*)&Vg[(size_t)(k0+row)*HD + c];
        }
        if (tid < 64) Kval[tid] = (ids[b*SEQ + k0 + tid] != 0) ? 1.0f : 0.0f;
        __syncthreads();

        float s[8];
#pragma unroll
        for (int jj = 0; jj < 8; jj++) s[jj] = 0.f;
#pragma unroll 4
        for (int d = 0; d < 128; d += 4) {
            float4 qv = *(const float4*)&Qs[r*128 + d];
#pragma unroll
            for (int jj = 0; jj < 8; jj++) {
                float4 kv = *(const float4*)&Ks[(g*8+jj)*128 + d];
                s[jj] += qv.x*kv.x + qv.y*kv.y + qv.z*kv.z + qv.w*kv.w;
            }
        }
        float tmax = -1e30f;
#pragma unroll
        for (int jj = 0; jj < 8; jj++) {
            int kpos = k0 + g*8 + jj;
            float sv = s[jj] * 0.08838834764831845f;
            if (kpos > qpos + 1 || Kval[g*8+jj] == 0.0f) sv = -1e30f;
            s[jj] = sv;
            tmax = fmaxf(tmax, sv);
        }
        tmax = fmaxf(tmax, __shfl_xor_sync(0xffffffffu, tmax, 1, 8));
        tmax = fmaxf(tmax, __shfl_xor_sync(0xffffffffu, tmax, 2, 8));
        tmax = fmaxf(tmax, __shfl_xor_sync(0xffffffffu, tmax, 4, 8));
        float mnew  = fmaxf(mrun, tmax);
        float scale = __expf(mrun - mnew);
        float psum  = 0.f;
#pragma unroll
        for (int jj = 0; jj < 8; jj++) {
            float p = (s[jj] <= -1e29f) ? 0.f : __expf(s[jj] - mnew);
            s[jj] = p; psum += p;
        }
        psum += __shfl_xor_sync(0xffffffffu, psum, 1, 8);
        psum += __shfl_xor_sync(0xffffffffu, psum, 2, 8);
        psum += __shfl_xor_sync(0xffffffffu, psum, 4, 8);
        lrun = lrun * scale + psum;
        mrun = mnew;
        acc0.x*=scale; acc0.y*=scale; acc0.z*=scale; acc0.w*=scale;
        acc1.x*=scale; acc1.y*=scale; acc1.z*=scale; acc1.w*=scale;
        acc2.x*=scale; acc2.y*=scale; acc2.z*=scale; acc2.w*=scale;
        acc3.x*=scale; acc3.y*=scale; acc3.z*=scale; acc3.w*=scale;
#pragma unroll
        for (int jj = 0; jj < 8; jj++) Sm[r*64 + g*8 + jj] = s[jj];
        __syncthreads();

#pragma unroll 4
        for (int j = 0; j < 64; j++) {
            float p = Sm[r*64 + j];
            const float* vrow = &Vs[j*128 + cb];
            float4 v0 = *(const float4*)(vrow);
            float4 v1 = *(const float4*)(vrow + 32);
            float4 v2 = *(const float4*)(vrow + 64);
            float4 v3 = *(const float4*)(vrow + 96);
            acc0.x = fmaf(p, v0.x, acc0.x); acc0.y = fmaf(p, v0.y, acc0.y);
            acc0.z = fmaf(p, v0.z, acc0.z); acc0.w = fmaf(p, v0.w, acc0.w);
            acc1.x = fmaf(p, v1.x, acc1.x); acc1.y = fmaf(p, v1.y, acc1.y);
            acc1.z = fmaf(p, v1.z, acc1.z); acc1.w = fmaf(p, v1.w, acc1.w);
            acc2.x = fmaf(p, v2.x, acc2.x); acc2.y = fmaf(p, v2.y, acc2.y);
            acc2.z = fmaf(p, v2.z, acc2.z); acc2.w = fmaf(p, v2.w, acc2.w);
            acc3.x = fmaf(p, v3.x, acc3.x); acc3.y = fmaf(p, v3.y, acc3.y);
            acc3.z = fmaf(p, v3.z, acc3.z); acc3.w = fmaf(p, v3.w, acc3.w);
        }
    }

    float inv = 1.0f / lrun;
    float* Og = O + ((size_t)(b*SEQ + qpos))*HID + h*HD;
    float4 o;
    o = make_float4(acc0.x*inv, acc0.y*inv, acc0.z*inv, acc0.w*inv); *(float4*)&Og[cb     ] = o;
    o = make_float4(acc1.x*inv, acc1.y*inv, acc1.z*inv, acc1.w*inv); *(float4*)&Og[cb + 32] = o;
    o = make_float4(acc2.x*inv, acc2.y*inv, acc2.z*inv, acc2.w*inv); *(float4*)&Og[cb + 64] = o;
    o = make_float4(acc3.x*inv, acc3.y*inv, acc3.z*inv, acc3.w*inv); *(float4*)&Og[cb + 96] = o;
}

// Tail: reference returns (out, start_pos + Tq) — fill any extra output slots.
__global__ void tail_kernel(float* __restrict__ out, const int* __restrict__ sp, int out_size)
{
    int i = MROWS*HID + blockIdx.x*blockDim.x + threadIdx.x;
    if (i < out_size) {
        int s = sp ? *sp : 0;
        out[i] = (float)(s + SEQ);
    }
}

// ---------------------------------------------------------------------------
extern "C" void kernel_launch(void* const* d_in, const int* in_sizes, int n_in,
                              void* d_out, int out_size)
{
    const int*   ids    = (const int*)  d_in[0];
    const float* hidden = (const float*)d_in[1];
    const float* Wq     = (const float*)d_in[2];
    const float* Wk     = (const float*)d_in[3];
    const float* Wv     = (const float*)d_in[4];
    const float* Wo     = (const float*)d_in[5];
    float*       out    = (float*)d_out;

    float *qb, *kb, *vb, *ob, *hr, *orr, *wqr, *wkr, *wvr, *wor;
    cudaGetSymbolAddress((void**)&qb,  g_q);
    cudaGetSymbolAddress((void**)&kb,  g_k);
    cudaGetSymbolAddress((void**)&vb,  g_v);
    cudaGetSymbolAddress((void**)&ob,  g_o);
    cudaGetSymbolAddress((void**)&hr,  g_hr);
    cudaGetSymbolAddress((void**)&orr, g_or);
    cudaGetSymbolAddress((void**)&wqr, g_wqr);
    cudaGetSymbolAddress((void**)&wkr, g_wkr);
    cudaGetSymbolAddress((void**)&wvr, g_wvr);
    cudaGetSymbolAddress((void**)&wor, g_wor);

    cudaFuncSetAttribute(gemm_tf32<0>, cudaFuncAttributeMaxDynamicSharedMemorySize, GEMM_SMEM);
    cudaFuncSetAttribute(gemm_tf32<1>, cudaFuncAttributeMaxDynamicSharedMemorySize, GEMM_SMEM);
    cudaFuncSetAttribute(gemm_tf32<2>, cudaFuncAttributeMaxDynamicSharedMemorySize, GEMM_SMEM);

    auto round_launch = [&](float* d, const float* s, size_t n) {
        int n4 = (int)(n / 4);
        round_tf32_kernel<<<(n4 + 255)/256, 256>>>(d, s, n4);
    };
    round_launch(hr,  hidden, (size_t)MROWS*HID);
    round_launch(wqr, Wq,     (size_t)HID*HID);
    round_launch(wkr, Wk,     (size_t)NKV*HD*HID);
    round_launch(wvr, Wv,     (size_t)NKV*HD*HID);
    round_launch(wor, Wo,     (size_t)HID*HID);

    dim3 blk(256);
    gemm_tf32<1><<<dim3(HID/128,      MROWS/128), blk, GEMM_SMEM>>>(hr, wqr, qb, HID,    HID);
    gemm_tf32<2><<<dim3((NKV*HD)/128, MROWS/128), blk, GEMM_SMEM>>>(hr, wkr, kb, NKV*HD, HID);
    gemm_tf32<2><<<dim3((NKV*HD)/128, MROWS/128), blk, GEMM_SMEM>>>(hr, wvr, vb, NKV*HD, HID);

    const size_t asmem = (size_t)(32*128 + 2*64*128 + 32*64 + 64) * sizeof(float);
    cudaFuncSetAttribute(attn_kernel, cudaFuncAttributeMaxDynamicSharedMemorySize, (int)asmem);
    attn_kernel<<<dim3(SEQ/32, NH, BATCH), blk, asmem>>>(ids, ob);

    round_launch(orr, ob, (size_t)MROWS*HID);
    gemm_tf32<0><<<dim3(HID/128, MROWS/128), blk, GEMM_SMEM>>>(orr, wor, out, HID, HID);

    if (out_size > MROWS*HID) {
        int rem = out_size - MROWS*HID;
        const int* sp = (n_in > 8) ? (const int*)d_in[8] : nullptr;
        tail_kernel<<<(rem + 127)/128, 128>>>(out, sp, out_size);
    }
}

// round 6
// speedup vs baseline: 1.5970x; 1.1281x over previous
#include <cuda_runtime.h>
#include <cuda_fp16.h>
#include <cstdint>

#define HID   4096
#define NH    32
#define NKV   8
#define HD    128
#define BATCH 4
#define SEQ   1024
#define MROWS (BATCH*SEQ)   // 4096

// ---------------------------------------------------------------------------
// Scratch (static __device__ — no allocations allowed)
// ---------------------------------------------------------------------------
__device__ float g_q [(size_t)BATCH*NH *SEQ*HD];   // (b,h,t,d)
__device__ float g_k [(size_t)BATCH*NKV*SEQ*HD];   // (b,kvh,t,d)
__device__ float g_v [(size_t)BATCH*NKV*SEQ*HD];
__device__ float g_o [(size_t)MROWS*HID];          // attention out (f32)
// fp16 operand copies
__device__ __half g_hh [(size_t)MROWS*HID];
__device__ __half g_oh [(size_t)MROWS*HID];
__device__ __half g_wqh[(size_t)HID*HID];
__device__ __half g_wkh[(size_t)NKV*HD*HID];
__device__ __half g_wvh[(size_t)NKV*HD*HID];
__device__ __half g_woh[(size_t)HID*HID];

// ---------------------------------------------------------------------------
__device__ __forceinline__ uint32_t h2_as_u32(__half2 h) {
    uint32_t u;
    memcpy(&u, &h, 4);
    return u;
}
__device__ __forceinline__ void cpasync16s(uint32_t s, const void* g) {
    asm volatile("cp.async.cg.shared.global [%0], [%1], 16;" :: "r"(s), "l"(g));
}
#define CP_COMMIT() asm volatile("cp.async.commit_group;")
#define CP_WAIT(n)  asm volatile("cp.async.wait_group %0;" :: "n"(n))

#define LDMX4(r0,r1,r2,r3, addr) \
    asm volatile("ldmatrix.sync.aligned.m8n8.x4.shared.b16 {%0,%1,%2,%3}, [%4];" \
        : "=r"(r0), "=r"(r1), "=r"(r2), "=r"(r3) : "r"(addr))

#define MMA16(d, a, b0, b1) \
    asm volatile("mma.sync.aligned.m16n8k16.row.col.f32.f16.f16.f32 " \
        "{%0,%1,%2,%3}, {%4,%5,%6,%7}, {%8,%9}, {%0,%1,%2,%3};" \
        : "+f"((d)[0]), "+f"((d)[1]), "+f"((d)[2]), "+f"((d)[3]) \
        : "r"((a)[0]), "r"((a)[1]), "r"((a)[2]), "r"((a)[3]), "r"(b0), "r"(b1))

// ---------------------------------------------------------------------------
// FP16 mma.sync GEMM:  C[M,N] = A[M,K] * B[N,K]^T  (fp16 in, f32 out)
// 128x128 CTA tile, BK=64 (128B rows, XOR swizzle), 3-stage cp.async (96KB),
// 256 threads (8 warps, warp tile 64x32), m16n8k16 via ldmatrix.x4.
// MODE 0: C[m*N+n]; MODE 1: scatter (b,h,t,d) 32 heads; MODE 2: 8 heads.
// ---------------------------------------------------------------------------
#define STAGE_BYTES (128*128)            // 128 rows * 128B
#define GEMM_SMEM   (3*2*STAGE_BYTES)    // 96 KB

template<int MODE>
__global__ __launch_bounds__(256, 1)
void gemm_f16(const __half* __restrict__ A, const __half* __restrict__ Bw,
              float* __restrict__ C, int N, int K)
{
    extern __shared__ __align__(128) uint8_t sm[];
    const uint32_t sbase = (uint32_t)__cvta_generic_to_shared(sm);
    const uint32_t aB0 = sbase;
    const uint32_t bB0 = sbase + 3*STAGE_BYTES;

    const int tid  = threadIdx.x;
    const int w    = tid >> 5;
    const int lane = tid & 31;
    const int wm   = (w & 1) * 64;
    const int wn   = (w >> 1) * 32;
    const int mBase = blockIdx.y << 7;
    const int nBase = blockIdx.x << 7;
    const __half* Ag = A  + (size_t)mBase * K;
    const __half* Bg = Bw + (size_t)nBase * K;

    // ldmatrix lane geometry
    const int ar  = wm + ((lane >> 3) & 1) * 8 + (lane & 7);  // A row (+16*mt)
    const int ahi = lane >> 4;                                 // A k-chunk bit
    const int br  = wn + ((lane >> 4) & 1) * 8 + (lane & 7);  // B row (+16*p)
    const int bhi = (lane >> 3) & 1;                           // B k-chunk bit
    const int asw = ar & 7;
    const int bsw = br & 7;

    float acc[4][4][4];
#pragma unroll
    for (int i = 0; i < 4; i++)
#pragma unroll
        for (int j = 0; j < 4; j++)
#pragma unroll
            for (int r = 0; r < 4; r++) acc[i][j][r] = 0.f;

    // cp.async: per stage per array 1024 16B chunks; thread covers 4 each.
    auto issue = [&](int kt) {
        const int st = kt - (kt/3)*3;
        const int k0 = kt << 6;
        const uint32_t aS = aB0 + st*STAGE_BYTES;
        const uint32_t bS = bB0 + st*STAGE_BYTES;
#pragma unroll
        for (int i = 0; i < 4; i++) {
            int slot = tid + (i << 8);
            int r = slot >> 3;           // row 0..127
            int c = slot & 7;            // 16B chunk 0..7
            uint32_t dst = (uint32_t)(r*128 + ((c ^ (r & 7)) << 4));
            cpasync16s(aS + dst, Ag + (size_t)r * K + k0 + c*8);
            cpasync16s(bS + dst, Bg + (size_t)r * K + k0 + c*8);
        }
    };

    const int kTiles = K >> 6;           // K/64
    issue(0); CP_COMMIT();
    issue(1); CP_COMMIT();

    for (int kt = 0; kt < kTiles; kt++) {
        CP_WAIT(1);
        __syncthreads();

        if (kt + 2 < kTiles) issue(kt + 2);
        CP_COMMIT();

        const int st = kt - (kt/3)*3;
        const uint32_t aS = aB0 + st*STAGE_BYTES;
        const uint32_t bS = bB0 + st*STAGE_BYTES;

#pragma unroll
        for (int h = 0; h < 4; h++) {
            uint32_t a[4][4], b[2][4];
#pragma unroll
            for (int mt = 0; mt < 4; mt++) {
                uint32_t ad = aS + (uint32_t)((ar + mt*16)*128
                              + (((2*h + ahi) ^ asw) << 4));
                LDMX4(a[mt][0], a[mt][1], a[mt][2], a[mt][3], ad);
            }
#pragma unroll
            for (int p = 0; p < 2; p++) {
                uint32_t bd = bS + (uint32_t)((br + p*16)*128
                              + (((2*h + bhi) ^ bsw) << 4));
                LDMX4(b[p][0], b[p][1], b[p][2], b[p][3], bd);
            }
#pragma unroll
            for (int mt = 0; mt < 4; mt++) {
                MMA16(acc[mt][0], a[mt], b[0][0], b[0][1]);
                MMA16(acc[mt][1], a[mt], b[0][2], b[0][3]);
                MMA16(acc[mt][2], a[mt], b[1][0], b[1][1]);
                MMA16(acc[mt][3], a[mt], b[1][2], b[1][3]);
            }
        }
    }

    // epilogue: frag c0,c1 -> (row lane/4, col 2*(lane%4)); c2,c3 -> row+8
    const int g = lane >> 2, t = lane & 3;
#pragma unroll
    for (int mt = 0; mt < 4; mt++) {
#pragma unroll
        for (int nt = 0; nt < 4; nt++) {
            int m = mBase + wm + mt*16 + g;
            int n = nBase + wn + nt*8 + 2*t;
#pragma unroll
            for (int half = 0; half < 2; half++) {
                int mm = m + half*8;
                float2 v = half ? make_float2(acc[mt][nt][2], acc[mt][nt][3])
                                : make_float2(acc[mt][nt][0], acc[mt][nt][1]);
                if (MODE == 0) {
                    *(float2*)&C[(size_t)mm * N + n] = v;
                } else {
                    int bb = mm >> 10, tk = mm & 1023;
                    int h2 = n >> 7, d = n & 127;
                    int heads = (MODE == 1) ? NH : NKV;
                    *(float2*)&C[(((size_t)(bb*heads + h2))*SEQ + tk)*HD + d] = v;
                }
            }
        }
    }
}

// ---------------------------------------------------------------------------
// f32 -> fp16 conversion pre-pass (8 elems/thread)
// ---------------------------------------------------------------------------
__global__ void to_half_kernel(__half* __restrict__ dst, const float* __restrict__ src, int n8)
{
    int i = blockIdx.x * blockDim.x + threadIdx.x;
    if (i < n8) {
        float4 v0 = ((const float4*)src)[2*i];
        float4 v1 = ((const float4*)src)[2*i + 1];
        __half2 h0 = __floats2half2_rn(v0.x, v0.y);
        __half2 h1 = __floats2half2_rn(v0.z, v0.w);
        __half2 h2 = __floats2half2_rn(v1.x, v1.y);
        __half2 h3 = __floats2half2_rn(v1.z, v1.w);
        uint4 o;
        o.x = h2_as_u32(h0); o.y = h2_as_u32(h1);
        o.z = h2_as_u32(h2); o.w = h2_as_u32(h3);
        ((uint4*)dst)[i] = o;
    }
}

// ---------------------------------------------------------------------------
// Fused flash-style attention (fp32 SIMT, ~10us).
// Mask: kpos <= qpos+1 AND id[kpos]!=0; kv head = h % 8.
// ---------------------------------------------------------------------------
__global__ __launch_bounds__(256)
void attn_kernel(const int* __restrict__ ids, float* __restrict__ O)
{
    extern __shared__ float smf[];
    float* Qs   = smf;
    float* Ks   = Qs + 32*128;
    float* Vs   = Ks + 64*128;
    float* Sm   = Vs + 64*128;
    float* Kval = Sm + 32*64;

    const int q0  = blockIdx.x << 5;
    const int h   = blockIdx.y;
    const int b   = blockIdx.z;
    const int kvh = h & 7;
    const int tid = threadIdx.x;

    const float* Qg = g_q + ((size_t)(b*NH  + h  ))*SEQ*HD;
    const float* Kg = g_k + ((size_t)(b*NKV + kvh))*SEQ*HD;
    const float* Vg = g_v + ((size_t)(b*NKV + kvh))*SEQ*HD;

#pragma unroll
    for (int it = 0; it < 4; it++) {
        int f = tid + (it << 8);
        int row = f >> 5, c = (f & 31) << 2;
        *(float4*)&Qs[row*128 + c] = *(const float4*)&Qg[(size_t)(q0+row)*HD + c];
    }

    const int r = tid >> 3, g = tid & 7;
    const int qpos = q0 + r;
    const int cb = g << 2;

    float mrun = -1e30f, lrun = 0.f;
    float4 acc0 = make_float4(0,0,0,0), acc1 = acc0, acc2 = acc0, acc3 = acc0;

    const int kmax = q0 + 32;
    for (int k0 = 0; k0 <= kmax && k0 < SEQ; k0 += 64) {
        __syncthreads();
#pragma unroll
        for (int it = 0; it < 8; it++) {
            int f = tid + (it << 8);
            int row = f >> 5, c = (f & 31) << 2;
            *(float4*)&Ks[row*128 + c] = *(const float4*)&Kg[(size_t)(k0+row)*HD + c];
            *(float4*)&Vs[row*128 + c] = *(const float4*)&Vg[(size_t)(k0+row)*HD + c];
        }
        if (tid < 64) Kval[tid] = (ids[b*SEQ + k0 + tid] != 0) ? 1.0f : 0.0f;
        __syncthreads();

        float s[8];
#pragma unroll
        for (int jj = 0; jj < 8; jj++) s[jj] = 0.f;
#pragma unroll 4
        for (int d = 0; d < 128; d += 4) {
            float4 qv = *(const float4*)&Qs[r*128 + d];
#pragma unroll
            for (int jj = 0; jj < 8; jj++) {
                float4 kv = *(const float4*)&Ks[(g*8+jj)*128 + d];
                s[jj] += qv.x*kv.x + qv.y*kv.y + qv.z*kv.z + qv.w*kv.w;
            }
        }
        float tmax = -1e30f;
#pragma unroll
        for (int jj = 0; jj < 8; jj++) {
            int kpos = k0 + g*8 + jj;
            float sv = s[jj] * 0.08838834764831845f;
            if (kpos > qpos + 1 || Kval[g*8+jj] == 0.0f) sv = -1e30f;
            s[jj] = sv;
            tmax = fmaxf(tmax, sv);
        }
        tmax = fmaxf(tmax, __shfl_xor_sync(0xffffffffu, tmax, 1, 8));
        tmax = fmaxf(tmax, __shfl_xor_sync(0xffffffffu, tmax, 2, 8));
        tmax = fmaxf(tmax, __shfl_xor_sync(0xffffffffu, tmax, 4, 8));
        float mnew  = fmaxf(mrun, tmax);
        float scale = __expf(mrun - mnew);
        float psum  = 0.f;
#pragma unroll
        for (int jj = 0; jj < 8; jj++) {
            float p = (s[jj] <= -1e29f) ? 0.f : __expf(s[jj] - mnew);
            s[jj] = p; psum += p;
        }
        psum += __shfl_xor_sync(0xffffffffu, psum, 1, 8);
        psum += __shfl_xor_sync(0xffffffffu, psum, 2, 8);
        psum += __shfl_xor_sync(0xffffffffu, psum, 4, 8);
        lrun = lrun * scale + psum;
        mrun = mnew;
        acc0.x*=scale; acc0.y*=scale; acc0.z*=scale; acc0.w*=scale;
        acc1.x*=scale; acc1.y*=scale; acc1.z*=scale; acc1.w*=scale;
        acc2.x*=scale; acc2.y*=scale; acc2.z*=scale; acc2.w*=scale;
        acc3.x*=scale; acc3.y*=scale; acc3.z*=scale; acc3.w*=scale;
#pragma unroll
        for (int jj = 0; jj < 8; jj++) Sm[r*64 + g*8 + jj] = s[jj];
        __syncthreads();

#pragma unroll 4
        for (int j = 0; j < 64; j++) {
            float p = Sm[r*64 + j];
            const float* vrow = &Vs[j*128 + cb];
            float4 v0 = *(const float4*)(vrow);
            float4 v1 = *(const float4*)(vrow + 32);
            float4 v2 = *(const float4*)(vrow + 64);
            float4 v3 = *(const float4*)(vrow + 96);
            acc0.x = fmaf(p, v0.x, acc0.x); acc0.y = fmaf(p, v0.y, acc0.y);
            acc0.z = fmaf(p, v0.z, acc0.z); acc0.w = fmaf(p, v0.w, acc0.w);
            acc1.x = fmaf(p, v1.x, acc1.x); acc1.y = fmaf(p, v1.y, acc1.y);
            acc1.z = fmaf(p, v1.z, acc1.z); acc1.w = fmaf(p, v1.w, acc1.w);
            acc2.x = fmaf(p, v2.x, acc2.x); acc2.y = fmaf(p, v2.y, acc2.y);
            acc2.z = fmaf(p, v2.z, acc2.z); acc2.w = fmaf(p, v2.w, acc2.w);
            acc3.x = fmaf(p, v3.x, acc3.x); acc3.y = fmaf(p, v3.y, acc3.y);
            acc3.z = fmaf(p, v3.z, acc3.z); acc3.w = fmaf(p, v3.w, acc3.w);
        }
    }

    float inv = 1.0f / lrun;
    float* Og = O + ((size_t)(b*SEQ + qpos))*HID + h*HD;
    float4 o;
    o = make_float4(acc0.x*inv, acc0.y*inv, acc0.z*inv, acc0.w*inv); *(float4*)&Og[cb     ] = o;
    o = make_float4(acc1.x*inv, acc1.y*inv, acc1.z*inv, acc1.w*inv); *(float4*)&Og[cb + 32] = o;
    o = make_float4(acc2.x*inv, acc2.y*inv, acc2.z*inv, acc2.w*inv); *(float4*)&Og[cb + 64] = o;
    o = make_float4(acc3.x*inv, acc3.y*inv, acc3.z*inv, acc3.w*inv); *(float4*)&Og[cb + 96] = o;
}

// Tail: reference returns (out, start_pos + Tq) — fill any extra output slots.
__global__ void tail_kernel(float* __restrict__ out, const int* __restrict__ sp, int out_size)
{
    int i = MROWS*HID + blockIdx.x*blockDim.x + threadIdx.x;
    if (i < out_size) {
        int s = sp ? *sp : 0;
        out[i] = (float)(s + SEQ);
    }
}

// ---------------------------------------------------------------------------
extern "C" void kernel_launch(void* const* d_in, const int* in_sizes, int n_in,
                              void* d_out, int out_size)
{
    const int*   ids    = (const int*)  d_in[0];
    const float* hidden = (const float*)d_in[1];
    const float* Wq     = (const float*)d_in[2];
    const float* Wk     = (const float*)d_in[3];
    const float* Wv     = (const float*)d_in[4];
    const float* Wo     = (const float*)d_in[5];
    float*       out    = (float*)d_out;

    float *qb, *kb, *vb, *ob;
    __half *hh, *oh, *wqh, *wkh, *wvh, *woh;
    cudaGetSymbolAddress((void**)&qb,  g_q);
    cudaGetSymbolAddress((void**)&kb,  g_k);
    cudaGetSymbolAddress((void**)&vb,  g_v);
    cudaGetSymbolAddress((void**)&ob,  g_o);
    cudaGetSymbolAddress((void**)&hh,  g_hh);
    cudaGetSymbolAddress((void**)&oh,  g_oh);
    cudaGetSymbolAddress((void**)&wqh, g_wqh);
    cudaGetSymbolAddress((void**)&wkh, g_wkh);
    cudaGetSymbolAddress((void**)&wvh, g_wvh);
    cudaGetSymbolAddress((void**)&woh, g_woh);

    cudaFuncSetAttribute(gemm_f16<0>, cudaFuncAttributeMaxDynamicSharedMemorySize, GEMM_SMEM);
    cudaFuncSetAttribute(gemm_f16<1>, cudaFuncAttributeMaxDynamicSharedMemorySize, GEMM_SMEM);
    cudaFuncSetAttribute(gemm_f16<2>, cudaFuncAttributeMaxDynamicSharedMemorySize, GEMM_SMEM);

    auto conv = [&](__half* d, const float* s, size_t n) {
        int n8 = (int)(n / 8);
        to_half_kernel<<<(n8 + 255)/256, 256>>>(d, s, n8);
    };
    conv(hh,  hidden, (size_t)MROWS*HID);
    conv(wqh, Wq,     (size_t)HID*HID);
    conv(wkh, Wk,     (size_t)NKV*HD*HID);
    conv(wvh, Wv,     (size_t)NKV*HD*HID);
    conv(woh, Wo,     (size_t)HID*HID);

    dim3 blk(256);
    gemm_f16<1><<<dim3(HID/128,      MROWS/128), blk, GEMM_SMEM>>>(hh, wqh, qb, HID,    HID);
    gemm_f16<2><<<dim3((NKV*HD)/128, MROWS/128), blk, GEMM_SMEM>>>(hh, wkh, kb, NKV*HD, HID);
    gemm_f16<2><<<dim3((NKV*HD)/128, MROWS/128), blk, GEMM_SMEM>>>(hh, wvh, vb, NKV*HD, HID);

    const size_t asmem = (size_t)(32*128 + 2*64*128 + 32*64 + 64) * sizeof(float);
    cudaFuncSetAttribute(attn_kernel, cudaFuncAttributeMaxDynamicSharedMemorySize, (int)asmem);
    attn_kernel<<<dim3(SEQ/32, NH, BATCH), blk, asmem>>>(ids, ob);

    conv(oh, ob, (size_t)MROWS*HID);
    gemm_f16<0><<<dim3(HID/128, MROWS/128), blk, GEMM_SMEM>>>(oh, woh, out, HID, HID);

    if (out_size > MROWS*HID) {
        int rem = out_size - MROWS*HID;
        const int* sp = (n_in > 8) ? (const int*)d_in[8] : nullptr;
        tail_kernel<<<(rem + 127)/128, 128>>>(out, sp, out_size);
    }
}

// round 8
// speedup vs baseline: 1.6046x; 1.0048x over previous
#include <cuda_runtime.h>
#include <cuda_fp16.h>
#include <cstdint>

#define HID   4096
#define NH    32
#define NKV   8
#define HD    128
#define BATCH 4
#define SEQ   1024
#define MROWS (BATCH*SEQ)   // 4096

// ---------------------------------------------------------------------------
// Scratch (static __device__ — no allocations allowed)
// ---------------------------------------------------------------------------
__device__ float g_q [(size_t)BATCH*NH *SEQ*HD];   // (b,h,t,d)
__device__ float g_k [(size_t)BATCH*NKV*SEQ*HD];   // (b,kvh,t,d)
__device__ float g_v [(size_t)BATCH*NKV*SEQ*HD];
__device__ float g_o [(size_t)MROWS*HID];          // attention out (f32)
// fp16 operand copies
__device__ __half g_hh [(size_t)MROWS*HID];
__device__ __half g_oh [(size_t)MROWS*HID];
__device__ __half g_wqh[(size_t)HID*HID];
__device__ __half g_wkh[(size_t)NKV*HD*HID];
__device__ __half g_wvh[(size_t)NKV*HD*HID];
__device__ __half g_woh[(size_t)HID*HID];

// ---------------------------------------------------------------------------
__device__ __forceinline__ uint32_t h2_as_u32(__half2 h) {
    uint32_t u;
    memcpy(&u, &h, 4);
    return u;
}
__device__ __forceinline__ void cpasync16s(uint32_t s, const void* g) {
    asm volatile("cp.async.cg.shared.global [%0], [%1], 16;" :: "r"(s), "l"(g));
}
#define CP_COMMIT() asm volatile("cp.async.commit_group;")
#define CP_WAIT(n)  asm volatile("cp.async.wait_group %0;" :: "n"(n))

#define LDMX4(r0,r1,r2,r3, addr) \
    asm volatile("ldmatrix.sync.aligned.m8n8.x4.shared.b16 {%0,%1,%2,%3}, [%4];" \
        : "=r"(r0), "=r"(r1), "=r"(r2), "=r"(r3) : "r"(addr))

#define MMA16(d, a, b0, b1) \
    asm volatile("mma.sync.aligned.m16n8k16.row.col.f32.f16.f16.f32 " \
        "{%0,%1,%2,%3}, {%4,%5,%6,%7}, {%8,%9}, {%0,%1,%2,%3};" \
        : "+f"((d)[0]), "+f"((d)[1]), "+f"((d)[2]), "+f"((d)[3]) \
        : "r"((a)[0]), "r"((a)[1]), "r"((a)[2]), "r"((a)[3]), "r"(b0), "r"(b1))

// ---------------------------------------------------------------------------
// FP16 mma.sync GEMM:  C[M,N] = A[M,K] * B[N,K]^T  (fp16 in, f32 out)
// 128x128 CTA tile, BK=32 (64B rows, XOR swizzle c ^ ((r>>1)&3)),
// 3-stage cp.async (48KB total -> 2 CTAs/SM), 256 threads (8 warps,
// warp tile 64x32), m16n8k16 via ldmatrix.x4.
// MODE 0: C[m*N+n]; MODE 1: scatter (b,h,t,d) 32 heads; MODE 2: 8 heads.
// ---------------------------------------------------------------------------
#define STAGE_BYTES (128*64)             // 128 rows * 64B (32 fp16)
#define GEMM_SMEM   (3*2*STAGE_BYTES)    // 48 KB

template<int MODE>
__global__ __launch_bounds__(256, 2)
void gemm_f16(const __half* __restrict__ A, const __half* __restrict__ Bw,
              float* __restrict__ C, int N, int K)
{
    extern __shared__ __align__(128) uint8_t sm[];
    const uint32_t sbase = (uint32_t)__cvta_generic_to_shared(sm);
    const uint32_t aB0 = sbase;
    const uint32_t bB0 = sbase + 3*STAGE_BYTES;

    const int tid  = threadIdx.x;
    const int w    = tid >> 5;
    const int lane = tid & 31;
    const int wm   = (w & 1) * 64;
    const int wn   = (w >> 1) * 32;
    const int mBase = blockIdx.y << 7;
    const int nBase = blockIdx.x << 7;
    const __half* Ag = A  + (size_t)mBase * K;
    const __half* Bg = Bw + (size_t)nBase * K;

    // ldmatrix lane geometry
    const int ar  = wm + ((lane >> 3) & 1) * 8 + (lane & 7);  // A row (+16*mt)
    const int ahi = lane >> 4;                                 // A 16B k-subchunk
    const int br  = wn + ((lane >> 4) & 1) * 8 + (lane & 7);  // B row (+16*p)
    const int bhi = (lane >> 3) & 1;                           // B 16B k-subchunk
    const int asw = (ar >> 1) & 3;   // swizzle idx (invariant under +16*mt)
    const int bsw = (br >> 1) & 3;

    float acc[4][4][4];
#pragma unroll
    for (int i = 0; i < 4; i++)
#pragma unroll
        for (int j = 0; j < 4; j++)
#pragma unroll
            for (int r = 0; r < 4; r++) acc[i][j][r] = 0.f;

    // cp.async: per stage per array 512 16B chunks; thread covers 2 each.
    auto issue = [&](int kt) {
        const int st = kt - (kt/3)*3;
        const int k0 = kt << 5;
        const uint32_t aS = aB0 + st*STAGE_BYTES;
        const uint32_t bS = bB0 + st*STAGE_BYTES;
#pragma unroll
        for (int i = 0; i < 2; i++) {
            int slot = tid + (i << 8);
            int r = slot >> 2;           // row 0..127
            int c = slot & 3;            // 16B chunk 0..3
            uint32_t dst = (uint32_t)(r*64 + ((c ^ ((r >> 1) & 3)) << 4));
            cpasync16s(aS + dst, Ag + (size_t)r * K + k0 + c*8);
            cpasync16s(bS + dst, Bg + (size_t)r * K + k0 + c*8);
        }
    };

    const int kTiles = K >> 5;           // K/32
    issue(0); CP_COMMIT();
    issue(1); CP_COMMIT();

    for (int kt = 0; kt < kTiles; kt++) {
        CP_WAIT(1);
        __syncthreads();

        if (kt + 2 < kTiles) issue(kt + 2);
        CP_COMMIT();

        const int st = kt - (kt/3)*3;
        const uint32_t aS = aB0 + st*STAGE_BYTES;
        const uint32_t bS = bB0 + st*STAGE_BYTES;

#pragma unroll
        for (int h = 0; h < 2; h++) {
            uint32_t a[4][4], b[2][4];
#pragma unroll
            for (int mt = 0; mt < 4; mt++) {
                uint32_t ad = aS + (uint32_t)((ar + mt*16)*64
                              + (((2*h + ahi) ^ asw) << 4));
                LDMX4(a[mt][0], a[mt][1], a[mt][2], a[mt][3], ad);
            }
#pragma unroll
            for (int p = 0; p < 2; p++) {
                uint32_t bd = bS + (uint32_t)((br + p*16)*64
                              + (((2*h + bhi) ^ bsw) << 4));
                LDMX4(b[p][0], b[p][1], b[p][2], b[p][3], bd);
            }
#pragma unroll
            for (int mt = 0; mt < 4; mt++) {
                MMA16(acc[mt][0], a[mt], b[0][0], b[0][1]);
                MMA16(acc[mt][1], a[mt], b[0][2], b[0][3]);
                MMA16(acc[mt][2], a[mt], b[1][0], b[1][1]);
                MMA16(acc[mt][3], a[mt], b[1][2], b[1][3]);
            }
        }
    }

    // epilogue: frag c0,c1 -> (row lane/4, col 2*(lane%4)); c2,c3 -> row+8
    const int g = lane >> 2, t = lane & 3;
#pragma unroll
    for (int mt = 0; mt < 4; mt++) {
#pragma unroll
        for (int nt = 0; nt < 4; nt++) {
            int m = mBase + wm + mt*16 + g;
            int n = nBase + wn + nt*8 + 2*t;
#pragma unroll
            for (int half = 0; half < 2; half++) {
                int mm = m + half*8;
                float2 v = half ? make_float2(acc[mt][nt][2], acc[mt][nt][3])
                                : make_float2(acc[mt][nt][0], acc[mt][nt][1]);
                if (MODE == 0) {
                    *(float2*)&C[(size_t)mm * N + n] = v;
                } else {
                    int bb = mm >> 10, tk = mm & 1023;
                    int h2 = n >> 7, d = n & 127;
                    int heads = (MODE == 1) ? NH : NKV;
                    *(float2*)&C[(((size_t)(bb*heads + h2))*SEQ + tk)*HD + d] = v;
                }
            }
        }
    }
}

// ---------------------------------------------------------------------------
// f32 -> fp16 conversion pre-pass (8 elems/thread)
// ---------------------------------------------------------------------------
__global__ void to_half_kernel(__half* __restrict__ dst, const float* __restrict__ src, int n8)
{
    int i = blockIdx.x * blockDim.x + threadIdx.x;
    if (i < n8) {
        float4 v0 = ((const float4*)src)[2*i];
        float4 v1 = ((const float4*)src)[2*i + 1];
        __half2 h0 = __floats2half2_rn(v0.x, v0.y);
        __half2 h1 = __floats2half2_rn(v0.z, v0.w);
        __half2 h2 = __floats2half2_rn(v1.x, v1.y);
        __half2 h3 = __floats2half2_rn(v1.z, v1.w);
        uint4 o;
        o.x = h2_as_u32(h0); o.y = h2_as_u32(h1);
        o.z = h2_as_u32(h2); o.w = h2_as_u32(h3);
        ((uint4*)dst)[i] = o;
    }
}

// ---------------------------------------------------------------------------
// Fused flash-style attention (fp32 SIMT, ~10us).
// Mask: kpos <= qpos+1 AND id[kpos]!=0; kv head = h % 8.
// ---------------------------------------------------------------------------
__global__ __launch_bounds__(256)
void attn_kernel(const int* __restrict__ ids, float* __restrict__ O)
{
    extern __shared__ float smf[];
    float* Qs   = smf;
    float* Ks   = Qs + 32*128;
    float* Vs   = Ks + 64*128;
    float* Sm   = Vs + 64*128;
    float* Kval = Sm + 32*64;

    const int q0  = blockIdx.x << 5;
    const int h   = blockIdx.y;
    const int b   = blockIdx.z;
    const int kvh = h & 7;
    const int tid = threadIdx.x;

    const float* Qg = g_q + ((size_t)(b*NH  + h  ))*SEQ*HD;
    const float* Kg = g_k + ((size_t)(b*NKV + kvh))*SEQ*HD;
    const float* Vg = g_v + ((size_t)(b*NKV + kvh))*SEQ*HD;

#pragma unroll
    for (int it = 0; it < 4; it++) {
        int f = tid + (it << 8);
        int row = f >> 5, c = (f & 31) << 2;
        *(float4*)&Qs[row*128 + c] = *(const float4*)&Qg[(size_t)(q0+row)*HD + c];
    }

    const int r = tid >> 3, g = tid & 7;
    const int qpos = q0 + r;
    const int cb = g << 2;

    float mrun = -1e30f, lrun = 0.f;
    float4 acc0 = make_float4(0,0,0,0), acc1 = acc0, acc2 = acc0, acc3 = acc0;

    const int kmax = q0 + 32;
    for (int k0 = 0; k0 <= kmax && k0 < SEQ; k0 += 64) {
        __syncthreads();
#pragma unroll
        for (int it = 0; it < 8; it++) {
            int f = tid + (it << 8);
            int row = f >> 5, c = (f & 31) << 2;
            *(float4*)&Ks[row*128 + c] = *(const float4*)&Kg[(size_t)(k0+row)*HD + c];
            *(float4*)&Vs[row*128 + c] = *(const float4*)&Vg[(size_t)(k0+row)*HD + c];
        }
        if (tid < 64) Kval[tid] = (ids[b*SEQ + k0 + tid] != 0) ? 1.0f : 0.0f;
        __syncthreads();

        float s[8];
#pragma unroll
        for (int jj = 0; jj < 8; jj++) s[jj] = 0.f;
#pragma unroll 4
        for (int d = 0; d < 128; d += 4) {
            float4 qv = *(const float4*)&Qs[r*128 + d];
#pragma unroll
            for (int jj = 0; jj < 8; jj++) {
                float4 kv = *(const float4*)&Ks[(g*8+jj)*128 + d];
                s[jj] += qv.x*kv.x + qv.y*kv.y + qv.z*kv.z + qv.w*kv.w;
            }
        }
        float tmax = -1e30f;
#pragma unroll
        for (int jj = 0; jj < 8; jj++) {
            int kpos = k0 + g*8 + jj;
            float sv = s[jj] * 0.08838834764831845f;
            if (kpos > qpos + 1 || Kval[g*8+jj] == 0.0f) sv = -1e30f;
            s[jj] = sv;
            tmax = fmaxf(tmax, sv);
        }
        tmax = fmaxf(tmax, __shfl_xor_sync(0xffffffffu, tmax, 1, 8));
        tmax = fmaxf(tmax, __shfl_xor_sync(0xffffffffu, tmax, 2, 8));
        tmax = fmaxf(tmax, __shfl_xor_sync(0xffffffffu, tmax, 4, 8));
        float mnew  = fmaxf(mrun, tmax);
        float scale = __expf(mrun - mnew);
        float psum  = 0.f;
#pragma unroll
        for (int jj = 0; jj < 8; jj++) {
            float p = (s[jj] <= -1e29f) ? 0.f : __expf(s[jj] - mnew);
            s[jj] = p; psum += p;
        }
        psum += __shfl_xor_sync(0xffffffffu, psum, 1, 8);
        psum += __shfl_xor_sync(0xffffffffu, psum, 2, 8);
        psum += __shfl_xor_sync(0xffffffffu, psum, 4, 8);
        lrun = lrun * scale + psum;
        mrun = mnew;
        acc0.x*=scale; acc0.y*=scale; acc0.z*=scale; acc0.w*=scale;
        acc1.x*=scale; acc1.y*=scale; acc1.z*=scale; acc1.w*=scale;
        acc2.x*=scale; acc2.y*=scale; acc2.z*=scale; acc2.w*=scale;
        acc3.x*=scale; acc3.y*=scale; acc3.z*=scale; acc3.w*=scale;
#pragma unroll
        for (int jj = 0; jj < 8; jj++) Sm[r*64 + g*8 + jj] = s[jj];
        __syncthreads();

#pragma unroll 4
        for (int j = 0; j < 64; j++) {
            float p = Sm[r*64 + j];
            const float* vrow = &Vs[j*128 + cb];
            float4 v0 = *(const float4*)(vrow);
            float4 v1 = *(const float4*)(vrow + 32);
            float4 v2 = *(const float4*)(vrow + 64);
            float4 v3 = *(const float4*)(vrow + 96);
            acc0.x = fmaf(p, v0.x, acc0.x); acc0.y = fmaf(p, v0.y, acc0.y);
            acc0.z = fmaf(p, v0.z, acc0.z); acc0.w = fmaf(p, v0.w, acc0.w);
            acc1.x = fmaf(p, v1.x, acc1.x); acc1.y = fmaf(p, v1.y, acc1.y);
            acc1.z = fmaf(p, v1.z, acc1.z); acc1.w = fmaf(p, v1.w, acc1.w);
            acc2.x = fmaf(p, v2.x, acc2.x); acc2.y = fmaf(p, v2.y, acc2.y);
            acc2.z = fmaf(p, v2.z, acc2.z); acc2.w = fmaf(p, v2.w, acc2.w);
            acc3.x = fmaf(p, v3.x, acc3.x); acc3.y = fmaf(p, v3.y, acc3.y);
            acc3.z = fmaf(p, v3.z, acc3.z); acc3.w = fmaf(p, v3.w, acc3.w);
        }
    }

    float inv = 1.0f / lrun;
    float* Og = O + ((size_t)(b*SEQ + qpos))*HID + h*HD;
    float4 o;
    o = make_float4(acc0.x*inv, acc0.y*inv, acc0.z*inv, acc0.w*inv); *(float4*)&Og[cb     ] = o;
    o = make_float4(acc1.x*inv, acc1.y*inv, acc1.z*inv, acc1.w*inv); *(float4*)&Og[cb + 32] = o;
    o = make_float4(acc2.x*inv, acc2.y*inv, acc2.z*inv, acc2.w*inv); *(float4*)&Og[cb + 64] = o;
    o = make_float4(acc3.x*inv, acc3.y*inv, acc3.z*inv, acc3.w*inv); *(float4*)&Og[cb + 96] = o;
}

// Tail: reference returns (out, start_pos + Tq) — fill any extra output slots.
__global__ void tail_kernel(float* __restrict__ out, const int* __restrict__ sp, int out_size)
{
    int i = MROWS*HID + blockIdx.x*blockDim.x + threadIdx.x;
    if (i < out_size) {
        int s = sp ? *sp : 0;
        out[i] = (float)(s + SEQ);
    }
}

// ---------------------------------------------------------------------------
extern "C" void kernel_launch(void* const* d_in, const int* in_sizes, int n_in,
                              void* d_out, int out_size)
{
    const int*   ids    = (const int*)  d_in[0];
    const float* hidden = (const float*)d_in[1];
    const float* Wq     = (const float*)d_in[2];
    const float* Wk     = (const float*)d_in[3];
    const float* Wv     = (const float*)d_in[4];
    const float* Wo     = (const float*)d_in[5];
    float*       out    = (float*)d_out;

    float *qb, *kb, *vb, *ob;
    __half *hh, *oh, *wqh, *wkh, *wvh, *woh;
    cudaGetSymbolAddress((void**)&qb,  g_q);
    cudaGetSymbolAddress((void**)&kb,  g_k);
    cudaGetSymbolAddress((void**)&vb,  g_v);
    cudaGetSymbolAddress((void**)&ob,  g_o);
    cudaGetSymbolAddress((void**)&hh,  g_hh);
    cudaGetSymbolAddress((void**)&oh,  g_oh);
    cudaGetSymbolAddress((void**)&wqh, g_wqh);
    cudaGetSymbolAddress((void**)&wkh, g_wkh);
    cudaGetSymbolAddress((void**)&wvh, g_wvh);
    cudaGetSymbolAddress((void**)&woh, g_woh);

    cudaFuncSetAttribute(gemm_f16<0>, cudaFuncAttributeMaxDynamicSharedMemorySize, GEMM_SMEM);
    cudaFuncSetAttribute(gemm_f16<1>, cudaFuncAttributeMaxDynamicSharedMemorySize, GEMM_SMEM);
    cudaFuncSetAttribute(gemm_f16<2>, cudaFuncAttributeMaxDynamicSharedMemorySize, GEMM_SMEM);

    auto conv = [&](__half* d, const float* s, size_t n) {
        int n8 = (int)(n / 8);
        to_half_kernel<<<(n8 + 255)/256, 256>>>(d, s, n8);
    };

    dim3 blk(256);
    // Launch order chosen so gemm_f16<1> (Q GEMM) is the 5th kernel launch —
    // the harness's fixed ncu window (-s 5 -c 1) has been catching launch #5,
    // and we need the GEMM profile, not the conversion kernels.
    conv(hh,  hidden, (size_t)MROWS*HID);                                     // 1
    conv(wqh, Wq,     (size_t)HID*HID);                                       // 2
    conv(wkh, Wk,     (size_t)NKV*HD*HID);                                    // 3
    conv(wvh, Wv,     (size_t)NKV*HD*HID);                                    // 4
    gemm_f16<1><<<dim3(HID/128,      MROWS/128), blk, GEMM_SMEM>>>(hh, wqh, qb, HID,    HID); // 5
    conv(woh, Wo,     (size_t)HID*HID);                                       // 6
    gemm_f16<2><<<dim3((NKV*HD)/128, MROWS/128), blk, GEMM_SMEM>>>(hh, wkh, kb, NKV*HD, HID); // 7
    gemm_f16<2><<<dim3((NKV*HD)/128, MROWS/128), blk, GEMM_SMEM>>>(hh, wvh, vb, NKV*HD, HID); // 8

    const size_t asmem = (size_t)(32*128 + 2*64*128 + 32*64 + 64) * sizeof(float);
    cudaFuncSetAttribute(attn_kernel, cudaFuncAttributeMaxDynamicSharedMemorySize, (int)asmem);
    attn_kernel<<<dim3(SEQ/32, NH, BATCH), blk, asmem>>>(ids, ob);            // 9

    conv(oh, ob, (size_t)MROWS*HID);                                          // 10
    gemm_f16<0><<<dim3(HID/128, MROWS/128), blk, GEMM_SMEM>>>(oh, woh, out, HID, HID); // 11

    if (out_size > MROWS*HID) {
        int rem = out_size - MROWS*HID;
        const int* sp = (n_in > 8) ? (const int*)d_in[8] : nullptr;
        tail_kernel<<<(rem + 127)/128, 128>>>(out, sp, out_size);             // 12
    }
}

// round 10
// speedup vs baseline: 1.6049x; 1.0002x over previous
#include <cuda_runtime.h>
#include <cuda_fp16.h>
#include <cstdint>

#define HID   4096
#define NH    32
#define NKV   8
#define HD    128
#define BATCH 4
#define SEQ   1024
#define MROWS (BATCH*SEQ)   // 4096

// ---------------------------------------------------------------------------
// Scratch (static __device__ — no allocations allowed)
// ---------------------------------------------------------------------------
__device__ float g_q [(size_t)BATCH*NH *SEQ*HD];   // (b,h,t,d)
__device__ float g_k [(size_t)BATCH*NKV*SEQ*HD];   // (b,kvh,t,d)
__device__ float g_v [(size_t)BATCH*NKV*SEQ*HD];
__device__ float g_o [(size_t)MROWS*HID];          // attention out (f32)
// fp16 operand copies
__device__ __half g_hh [(size_t)MROWS*HID];
__device__ __half g_oh [(size_t)MROWS*HID];
__device__ __half g_wqh[(size_t)HID*HID];
__device__ __half g_wkh[(size_t)NKV*HD*HID];
__device__ __half g_wvh[(size_t)NKV*HD*HID];
__device__ __half g_woh[(size_t)HID*HID];

// ---------------------------------------------------------------------------
__device__ __forceinline__ uint32_t h2_as_u32(__half2 h) {
    uint32_t u;
    memcpy(&u, &h, 4);
    return u;
}
__device__ __forceinline__ void cpasync16s(uint32_t s, const void* g) {
    asm volatile("cp.async.cg.shared.global [%0], [%1], 16;" :: "r"(s), "l"(g));
}
#define CP_COMMIT() asm volatile("cp.async.commit_group;")
#define CP_WAIT(n)  asm volatile("cp.async.wait_group %0;" :: "n"(n))

#define LDMX4(r0,r1,r2,r3, addr) \
    asm volatile("ldmatrix.sync.aligned.m8n8.x4.shared.b16 {%0,%1,%2,%3}, [%4];" \
        : "=r"(r0), "=r"(r1), "=r"(r2), "=r"(r3) : "r"(addr))

#define MMA16(d, a, b0, b1) \
    asm volatile("mma.sync.aligned.m16n8k16.row.col.f32.f16.f16.f32 " \
        "{%0,%1,%2,%3}, {%4,%5,%6,%7}, {%8,%9}, {%0,%1,%2,%3};" \
        : "+f"((d)[0]), "+f"((d)[1]), "+f"((d)[2]), "+f"((d)[3]) \
        : "r"((a)[0]), "r"((a)[1]), "r"((a)[2]), "r"((a)[3]), "r"(b0), "r"(b1))

// ---------------------------------------------------------------------------
// FP16 mma.sync GEMM:  C[M,N] = A[M,K] * B[N,K]^T  (fp16 in, f32 out)
// 128x128 CTA tile, BK=32 (64B rows, XOR swizzle c ^ ((r>>1)&3)),
// 3-stage cp.async (48KB total -> 2 CTAs/SM), 256 threads (8 warps,
// warp tile 64x32), m16n8k16 via ldmatrix.x4.
// MODE 0: C[m*N+n]; MODE 1: scatter (b,h,t,d) 32 heads; MODE 2: 8 heads.
// ---------------------------------------------------------------------------
#define STAGE_BYTES (128*64)             // 128 rows * 64B (32 fp16)
#define GEMM_SMEM   (3*2*STAGE_BYTES)    // 48 KB

template<int MODE>
__global__ __launch_bounds__(256, 2)
void gemm_f16(const __half* __restrict__ A, const __half* __restrict__ Bw,
              float* __restrict__ C, int N, int K)
{
    extern __shared__ __align__(128) uint8_t sm[];
    const uint32_t sbase = (uint32_t)__cvta_generic_to_shared(sm);
    const uint32_t aB0 = sbase;
    const uint32_t bB0 = sbase + 3*STAGE_BYTES;

    const int tid  = threadIdx.x;
    const int w    = tid >> 5;
    const int lane = tid & 31;
    const int wm   = (w & 1) * 64;
    const int wn   = (w >> 1) * 32;
    const int mBase = blockIdx.y << 7;
    const int nBase = blockIdx.x << 7;
    const __half* Ag = A  + (size_t)mBase * K;
    const __half* Bg = Bw + (size_t)nBase * K;

    // ldmatrix lane geometry
    const int ar  = wm + ((lane >> 3) & 1) * 8 + (lane & 7);  // A row (+16*mt)
    const int ahi = lane >> 4;                                 // A 16B k-subchunk
    const int br  = wn + ((lane >> 4) & 1) * 8 + (lane & 7);  // B row (+16*p)
    const int bhi = (lane >> 3) & 1;                           // B 16B k-subchunk
    const int asw = (ar >> 1) & 3;   // swizzle idx (invariant under +16*mt)
    const int bsw = (br >> 1) & 3;

    float acc[4][4][4];
#pragma unroll
    for (int i = 0; i < 4; i++)
#pragma unroll
        for (int j = 0; j < 4; j++)
#pragma unroll
            for (int r = 0; r < 4; r++) acc[i][j][r] = 0.f;

    // cp.async: per stage per array 512 16B chunks; thread covers 2 each.
    auto issue = [&](int kt) {
        const int st = kt - (kt/3)*3;
        const int k0 = kt << 5;
        const uint32_t aS = aB0 + st*STAGE_BYTES;
        const uint32_t bS = bB0 + st*STAGE_BYTES;
#pragma unroll
        for (int i = 0; i < 2; i++) {
            int slot = tid + (i << 8);
            int r = slot >> 2;           // row 0..127
            int c = slot & 3;            // 16B chunk 0..3
            uint32_t dst = (uint32_t)(r*64 + ((c ^ ((r >> 1) & 3)) << 4));
            cpasync16s(aS + dst, Ag + (size_t)r * K + k0 + c*8);
            cpasync16s(bS + dst, Bg + (size_t)r * K + k0 + c*8);
        }
    };

    const int kTiles = K >> 5;           // K/32
    issue(0); CP_COMMIT();
    issue(1); CP_COMMIT();

    for (int kt = 0; kt < kTiles; kt++) {
        CP_WAIT(1);
        __syncthreads();

        if (kt + 2 < kTiles) issue(kt + 2);
        CP_COMMIT();

        const int st = kt - (kt/3)*3;
        const uint32_t aS = aB0 + st*STAGE_BYTES;
        const uint32_t bS = bB0 + st*STAGE_BYTES;

#pragma unroll
        for (int h = 0; h < 2; h++) {
            uint32_t a[4][4], b[2][4];
#pragma unroll
            for (int mt = 0; mt < 4; mt++) {
                uint32_t ad = aS + (uint32_t)((ar + mt*16)*64
                              + (((2*h + ahi) ^ asw) << 4));
                LDMX4(a[mt][0], a[mt][1], a[mt][2], a[mt][3], ad);
            }
#pragma unroll
            for (int p = 0; p < 2; p++) {
                uint32_t bd = bS + (uint32_t)((br + p*16)*64
                              + (((2*h + bhi) ^ bsw) << 4));
                LDMX4(b[p][0], b[p][1], b[p][2], b[p][3], bd);
            }
#pragma unroll
            for (int mt = 0; mt < 4; mt++) {
                MMA16(acc[mt][0], a[mt], b[0][0], b[0][1]);
                MMA16(acc[mt][1], a[mt], b[0][2], b[0][3]);
                MMA16(acc[mt][2], a[mt], b[1][0], b[1][1]);
                MMA16(acc[mt][3], a[mt], b[1][2], b[1][3]);
            }
        }
    }

    // epilogue: frag c0,c1 -> (row lane/4, col 2*(lane%4)); c2,c3 -> row+8
    const int g = lane >> 2, t = lane & 3;
#pragma unroll
    for (int mt = 0; mt < 4; mt++) {
#pragma unroll
        for (int nt = 0; nt < 4; nt++) {
            int m = mBase + wm + mt*16 + g;
            int n = nBase + wn + nt*8 + 2*t;
#pragma unroll
            for (int half = 0; half < 2; half++) {
                int mm = m + half*8;
                float2 v = half ? make_float2(acc[mt][nt][2], acc[mt][nt][3])
                                : make_float2(acc[mt][nt][0], acc[mt][nt][1]);
                if (MODE == 0) {
                    *(float2*)&C[(size_t)mm * N + n] = v;
                } else {
                    int bb = mm >> 10, tk = mm & 1023;
                    int h2 = n >> 7, d = n & 127;
                    int heads = (MODE == 1) ? NH : NKV;
                    *(float2*)&C[(((size_t)(bb*heads + h2))*SEQ + tk)*HD + d] = v;
                }
            }
        }
    }
}

// ---------------------------------------------------------------------------
// f32 -> fp16 conversion pre-pass (8 elems/thread)
// ---------------------------------------------------------------------------
__global__ void to_half_kernel(__half* __restrict__ dst, const float* __restrict__ src, int n8)
{
    int i = blockIdx.x * blockDim.x + threadIdx.x;
    if (i < n8) {
        float4 v0 = ((const float4*)src)[2*i];
        float4 v1 = ((const float4*)src)[2*i + 1];
        __half2 h0 = __floats2half2_rn(v0.x, v0.y);
        __half2 h1 = __floats2half2_rn(v0.z, v0.w);
        __half2 h2 = __floats2half2_rn(v1.x, v1.y);
        __half2 h3 = __floats2half2_rn(v1.z, v1.w);
        uint4 o;
        o.x = h2_as_u32(h0); o.y = h2_as_u32(h1);
        o.z = h2_as_u32(h2); o.w = h2_as_u32(h3);
        ((uint4*)dst)[i] = o;
    }
}

// ---------------------------------------------------------------------------
// Fused flash-style attention (fp32 SIMT, ~10us).
// Mask: kpos <= qpos+1 AND id[kpos]!=0; kv head = h % 8.
// ---------------------------------------------------------------------------
__global__ __launch_bounds__(256)
void attn_kernel(const int* __restrict__ ids, float* __restrict__ O)
{
    extern __shared__ float smf[];
    float* Qs   = smf;
    float* Ks   = Qs + 32*128;
    float* Vs   = Ks + 64*128;
    float* Sm   = Vs + 64*128;
    float* Kval = Sm + 32*64;

    const int q0  = blockIdx.x << 5;
    const int h   = blockIdx.y;
    const int b   = blockIdx.z;
    const int kvh = h & 7;
    const int tid = threadIdx.x;

    const float* Qg = g_q + ((size_t)(b*NH  + h  ))*SEQ*HD;
    const float* Kg = g_k + ((size_t)(b*NKV + kvh))*SEQ*HD;
    const float* Vg = g_v + ((size_t)(b*NKV + kvh))*SEQ*HD;

#pragma unroll
    for (int it = 0; it < 4; it++) {
        int f = tid + (it << 8);
        int row = f >> 5, c = (f & 31) << 2;
        *(float4*)&Qs[row*128 + c] = *(const float4*)&Qg[(size_t)(q0+row)*HD + c];
    }

    const int r = tid >> 3, g = tid & 7;
    const int qpos = q0 + r;
    const int cb = g << 2;

    float mrun = -1e30f, lrun = 0.f;
    float4 acc0 = make_float4(0,0,0,0), acc1 = acc0, acc2 = acc0, acc3 = acc0;

    const int kmax = q0 + 32;
    for (int k0 = 0; k0 <= kmax && k0 < SEQ; k0 += 64) {
        __syncthreads();
#pragma unroll
        for (int it = 0; it < 8; it++) {
            int f = tid + (it << 8);
            int row = f >> 5, c = (f & 31) << 2;
            *(float4*)&Ks[row*128 + c] = *(const float4*)&Kg[(size_t)(k0+row)*HD + c];
            *(float4*)&Vs[row*128 + c] = *(const float4*)&Vg[(size_t)(k0+row)*HD + c];
        }
        if (tid < 64) Kval[tid] = (ids[b*SEQ + k0 + tid] != 0) ? 1.0f : 0.0f;
        __syncthreads();

        float s[8];
#pragma unroll
        for (int jj = 0; jj < 8; jj++) s[jj] = 0.f;
#pragma unroll 4
        for (int d = 0; d < 128; d += 4) {
            float4 qv = *(const float4*)&Qs[r*128 + d];
#pragma unroll
            for (int jj = 0; jj < 8; jj++) {
                float4 kv = *(const float4*)&Ks[(g*8+jj)*128 + d];
                s[jj] += qv.x*kv.x + qv.y*kv.y + qv.z*kv.z + qv.w*kv.w;
            }
        }
        float tmax = -1e30f;
#pragma unroll
        for (int jj = 0; jj < 8; jj++) {
            int kpos = k0 + g*8 + jj;
            float sv = s[jj] * 0.08838834764831845f;
            if (kpos > qpos + 1 || Kval[g*8+jj] == 0.0f) sv = -1e30f;
            s[jj] = sv;
            tmax = fmaxf(tmax, sv);
        }
        tmax = fmaxf(tmax, __shfl_xor_sync(0xffffffffu, tmax, 1, 8));
        tmax = fmaxf(tmax, __shfl_xor_sync(0xffffffffu, tmax, 2, 8));
        tmax = fmaxf(tmax, __shfl_xor_sync(0xffffffffu, tmax, 4, 8));
        float mnew  = fmaxf(mrun, tmax);
        float scale = __expf(mrun - mnew);
        float psum  = 0.f;
#pragma unroll
        for (int jj = 0; jj < 8; jj++) {
            float p = (s[jj] <= -1e29f) ? 0.f : __expf(s[jj] - mnew);
            s[jj] = p; psum += p;
        }
        psum += __shfl_xor_sync(0xffffffffu, psum, 1, 8);
        psum += __shfl_xor_sync(0xffffffffu, psum, 2, 8);
        psum += __shfl_xor_sync(0xffffffffu, psum, 4, 8);
        lrun = lrun * scale + psum;
        mrun = mnew;
        acc0.x*=scale; acc0.y*=scale; acc0.z*=scale; acc0.w*=scale;
        acc1.x*=scale; acc1.y*=scale; acc1.z*=scale; acc1.w*=scale;
        acc2.x*=scale; acc2.y*=scale; acc2.z*=scale; acc2.w*=scale;
        acc3.x*=scale; acc3.y*=scale; acc3.z*=scale; acc3.w*=scale;
#pragma unroll
        for (int jj = 0; jj < 8; jj++) Sm[r*64 + g*8 + jj] = s[jj];
        __syncthreads();

#pragma unroll 4
        for (int j = 0; j < 64; j++) {
            float p = Sm[r*64 + j];
            const float* vrow = &Vs[j*128 + cb];
            float4 v0 = *(const float4*)(vrow);
            float4 v1 = *(const float4*)(vrow + 32);
            float4 v2 = *(const float4*)(vrow + 64);
            float4 v3 = *(const float4*)(vrow + 96);
            acc0.x = fmaf(p, v0.x, acc0.x); acc0.y = fmaf(p, v0.y, acc0.y);
            acc0.z = fmaf(p, v0.z, acc0.z); acc0.w = fmaf(p, v0.w, acc0.w);
            acc1.x = fmaf(p, v1.x, acc1.x); acc1.y = fmaf(p, v1.y, acc1.y);
            acc1.z = fmaf(p, v1.z, acc1.z); acc1.w = fmaf(p, v1.w, acc1.w);
            acc2.x = fmaf(p, v2.x, acc2.x); acc2.y = fmaf(p, v2.y, acc2.y);
            acc2.z = fmaf(p, v2.z, acc2.z); acc2.w = fmaf(p, v2.w, acc2.w);
            acc3.x = fmaf(p, v3.x, acc3.x); acc3.y = fmaf(p, v3.y, acc3.y);
            acc3.z = fmaf(p, v3.z, acc3.z); acc3.w = fmaf(p, v3.w, acc3.w);
        }
    }

    float inv = 1.0f / lrun;
    float* Og = O + ((size_t)(b*SEQ + qpos))*HID + h*HD;
    float4 o;
    o = make_float4(acc0.x*inv, acc0.y*inv, acc0.z*inv, acc0.w*inv); *(float4*)&Og[cb     ] = o;
    o = make_float4(acc1.x*inv, acc1.y*inv, acc1.z*inv, acc1.w*inv); *(float4*)&Og[cb + 32] = o;
    o = make_float4(acc2.x*inv, acc2.y*inv, acc2.z*inv, acc2.w*inv); *(float4*)&Og[cb + 64] = o;
    o = make_float4(acc3.x*inv, acc3.y*inv, acc3.z*inv, acc3.w*inv); *(float4*)&Og[cb + 96] = o;
}

// Tail: reference returns (out, start_pos + Tq) — fill any extra output slots.
__global__ void tail_kernel(float* __restrict__ out, const int* __restrict__ sp, int out_size)
{
    int i = MROWS*HID + blockIdx.x*blockDim.x + threadIdx.x;
    if (i < out_size) {
        int s = sp ? *sp : 0;
        out[i] = (float)(s + SEQ);
    }
}

// ---------------------------------------------------------------------------
extern "C" void kernel_launch(void* const* d_in, const int* in_sizes, int n_in,
                              void* d_out, int out_size)
{
    const int*   ids    = (const int*)  d_in[0];
    const float* hidden = (const float*)d_in[1];
    const float* Wq     = (const float*)d_in[2];
    const float* Wk     = (const float*)d_in[3];
    const float* Wv     = (const float*)d_in[4];
    const float* Wo     = (const float*)d_in[5];
    float*       out    = (float*)d_out;

    float *qb, *kb, *vb, *ob;
    __half *hh, *oh, *wqh, *wkh, *wvh, *woh;
    cudaGetSymbolAddress((void**)&qb,  g_q);
    cudaGetSymbolAddress((void**)&kb,  g_k);
    cudaGetSymbolAddress((void**)&vb,  g_v);
    cudaGetSymbolAddress((void**)&ob,  g_o);
    cudaGetSymbolAddress((void**)&hh,  g_hh);
    cudaGetSymbolAddress((void**)&oh,  g_oh);
    cudaGetSymbolAddress((void**)&wqh, g_wqh);
    cudaGetSymbolAddress((void**)&wkh, g_wkh);
    cudaGetSymbolAddress((void**)&wvh, g_wvh);
    cudaGetSymbolAddress((void**)&woh, g_woh);

    cudaFuncSetAttribute(gemm_f16<0>, cudaFuncAttributeMaxDynamicSharedMemorySize, GEMM_SMEM);
    cudaFuncSetAttribute(gemm_f16<1>, cudaFuncAttributeMaxDynamicSharedMemorySize, GEMM_SMEM);
    cudaFuncSetAttribute(gemm_f16<2>, cudaFuncAttributeMaxDynamicSharedMemorySize, GEMM_SMEM);

    auto conv = [&](__half* d, const float* s, size_t n) {
        int n8 = (int)(n / 8);
        to_half_kernel<<<(n8 + 255)/256, 256>>>(d, s, n8);
    };

    dim3 blk(256);
    // Launch order: every profiled round so far captured launch #4
    // (r1/r2: attn, r4: round_tf32, r6/r8: to_half — all were launch #4).
    // Put the Q GEMM at position 4 to finally profile the bottleneck kernel.
    conv(hh,  hidden, (size_t)MROWS*HID);                                     // 1
    conv(wqh, Wq,     (size_t)HID*HID);                                       // 2
    conv(wkh, Wk,     (size_t)NKV*HD*HID);                                    // 3
    gemm_f16<1><<<dim3(HID/128,      MROWS/128), blk, GEMM_SMEM>>>(hh, wqh, qb, HID,    HID); // 4 <- profiled
    conv(wvh, Wv,     (size_t)NKV*HD*HID);                                    // 5
    conv(woh, Wo,     (size_t)HID*HID);                                       // 6
    gemm_f16<2><<<dim3((NKV*HD)/128, MROWS/128), blk, GEMM_SMEM>>>(hh, wkh, kb, NKV*HD, HID); // 7
    gemm_f16<2><<<dim3((NKV*HD)/128, MROWS/128), blk, GEMM_SMEM>>>(hh, wvh, vb, NKV*HD, HID); // 8

    const size_t asmem = (size_t)(32*128 + 2*64*128 + 32*64 + 64) * sizeof(float);
    cudaFuncSetAttribute(attn_kernel, cudaFuncAttributeMaxDynamicSharedMemorySize, (int)asmem);
    attn_kernel<<<dim3(SEQ/32, NH, BATCH), blk, asmem>>>(ids, ob);            // 9

    conv(oh, ob, (size_t)MROWS*HID);                                          // 10
    gemm_f16<0><<<dim3(HID/128, MROWS/128), blk, GEMM_SMEM>>>(oh, woh, out, HID, HID); // 11

    if (out_size > MROWS*HID) {
        int rem = out_size - MROWS*HID;
        const int* sp = (n_in > 8) ? (const int*)d_in[8] : nullptr;
        tail_kernel<<<(rem + 127)/128, 128>>>(out, sp, out_size);             // 12
    }
}

// round 11
// speedup vs baseline: 15.3949x; 9.5926x over previous
#include <cuda_runtime.h>
#include <cuda_fp16.h>
#include <cstdint>

#define HID   4096
#define NH    32
#define NKV   8
#define HD    128
#define BATCH 4
#define SEQ   1024
#define MROWS (BATCH*SEQ)   // 4096

// ---------------------------------------------------------------------------
// Scratch (static __device__ — no allocations allowed)
// ---------------------------------------------------------------------------
__device__ __half g_qh [(size_t)BATCH*NH *SEQ*HD];  // (b,h,t,d) fp16
__device__ __half g_kh [(size_t)BATCH*NKV*SEQ*HD];  // (b,kvh,t,d)
__device__ __half g_vh [(size_t)BATCH*NKV*SEQ*HD];
__device__ __half g_oh [(size_t)MROWS*HID];         // attention out fp16
__device__ __half g_hh [(size_t)MROWS*HID];         // hidden fp16
__device__ __half g_wqh[(size_t)HID*HID];
__device__ __half g_wkh[(size_t)NKV*HD*HID];
__device__ __half g_wvh[(size_t)NKV*HD*HID];
__device__ __half g_woh[(size_t)HID*HID];

// ---------------------------------------------------------------------------
__device__ __forceinline__ uint32_t h2_as_u32(__half2 h) {
    uint32_t u; memcpy(&u, &h, 4); return u;
}
__device__ __forceinline__ void cpasync16s(uint32_t s, const void* g) {
    asm volatile("cp.async.cg.shared.global [%0], [%1], 16;" :: "r"(s), "l"(g));
}
#define CP_COMMIT() asm volatile("cp.async.commit_group;")
#define CP_WAIT(n)  asm volatile("cp.async.wait_group %0;" :: "n"(n))

#define LDMX4(r0,r1,r2,r3, addr) \
    asm volatile("ldmatrix.sync.aligned.m8n8.x4.shared.b16 {%0,%1,%2,%3}, [%4];" \
        : "=r"(r0), "=r"(r1), "=r"(r2), "=r"(r3) : "r"(addr))

#define LDMX4T(r0,r1,r2,r3, addr) \
    asm volatile("ldmatrix.sync.aligned.m8n8.x4.trans.shared.b16 {%0,%1,%2,%3}, [%4];" \
        : "=r"(r0), "=r"(r1), "=r"(r2), "=r"(r3) : "r"(addr))

#define MMA16(d, a, b0, b1) \
    asm volatile("mma.sync.aligned.m16n8k16.row.col.f32.f16.f16.f32 " \
        "{%0,%1,%2,%3}, {%4,%5,%6,%7}, {%8,%9}, {%0,%1,%2,%3};" \
        : "+f"((d)[0]), "+f"((d)[1]), "+f"((d)[2]), "+f"((d)[3]) \
        : "r"((a)[0]), "r"((a)[1]), "r"((a)[2]), "r"((a)[3]), "r"(b0), "r"(b1))

// ---------------------------------------------------------------------------
// FP16 mma.sync GEMM:  C = A[M,K] * B[N,K]^T.  128x128 tile, BK=32, 3-stage
// cp.async, 8 warps (warp tile 64x32), m16n8k16 via ldmatrix.x4.
// MODE 0: f32 C[m*N+n]; MODE 1: fp16 scatter (b,h,t,d) 32 heads; MODE 2: 8.
// ---------------------------------------------------------------------------
#define STAGE_BYTES (128*64)
#define GEMM_SMEM   (3*2*STAGE_BYTES)    // 48 KB

template<int MODE>
__global__ __launch_bounds__(256, 2)
void gemm_f16(const __half* __restrict__ A, const __half* __restrict__ Bw,
              void* __restrict__ Cv, int N, int K)
{
    extern __shared__ __align__(128) uint8_t sm[];
    const uint32_t sbase = (uint32_t)__cvta_generic_to_shared(sm);
    const uint32_t aB0 = sbase;
    const uint32_t bB0 = sbase + 3*STAGE_BYTES;

    const int tid  = threadIdx.x;
    const int w    = tid >> 5;
    const int lane = tid & 31;
    const int wm   = (w & 1) * 64;
    const int wn   = (w >> 1) * 32;
    const int mBase = blockIdx.y << 7;
    const int nBase = blockIdx.x << 7;
    const __half* Ag = A  + (size_t)mBase * K;
    const __half* Bg = Bw + (size_t)nBase * K;

    const int ar  = wm + ((lane >> 3) & 1) * 8 + (lane & 7);
    const int ahi = lane >> 4;
    const int br  = wn + ((lane >> 4) & 1) * 8 + (lane & 7);
    const int bhi = (lane >> 3) & 1;
    const int asw = (ar >> 1) & 3;
    const int bsw = (br >> 1) & 3;

    float acc[4][4][4];
#pragma unroll
    for (int i = 0; i < 4; i++)
#pragma unroll
        for (int j = 0; j < 4; j++)
#pragma unroll
            for (int r = 0; r < 4; r++) acc[i][j][r] = 0.f;

    auto issue = [&](int kt) {
        const int st = kt - (kt/3)*3;
        const int k0 = kt << 5;
        const uint32_t aS = aB0 + st*STAGE_BYTES;
        const uint32_t bS = bB0 + st*STAGE_BYTES;
#pragma unroll
        for (int i = 0; i < 2; i++) {
            int slot = tid + (i << 8);
            int r = slot >> 2;
            int c = slot & 3;
            uint32_t dst = (uint32_t)(r*64 + ((c ^ ((r >> 1) & 3)) << 4));
            cpasync16s(aS + dst, Ag + (size_t)r * K + k0 + c*8);
            cpasync16s(bS + dst, Bg + (size_t)r * K + k0 + c*8);
        }
    };

    const int kTiles = K >> 5;
    issue(0); CP_COMMIT();
    issue(1); CP_COMMIT();

    for (int kt = 0; kt < kTiles; kt++) {
        CP_WAIT(1);
        __syncthreads();
        if (kt + 2 < kTiles) issue(kt + 2);
        CP_COMMIT();

        const int st = kt - (kt/3)*3;
        const uint32_t aS = aB0 + st*STAGE_BYTES;
        const uint32_t bS = bB0 + st*STAGE_BYTES;

#pragma unroll
        for (int h = 0; h < 2; h++) {
            uint32_t a[4][4], b[2][4];
#pragma unroll
            for (int mt = 0; mt < 4; mt++) {
                uint32_t ad = aS + (uint32_t)((ar + mt*16)*64
                              + (((2*h + ahi) ^ asw) << 4));
                LDMX4(a[mt][0], a[mt][1], a[mt][2], a[mt][3], ad);
            }
#pragma unroll
            for (int p = 0; p < 2; p++) {
                uint32_t bd = bS + (uint32_t)((br + p*16)*64
                              + (((2*h + bhi) ^ bsw) << 4));
                LDMX4(b[p][0], b[p][1], b[p][2], b[p][3], bd);
            }
#pragma unroll
            for (int mt = 0; mt < 4; mt++) {
                MMA16(acc[mt][0], a[mt], b[0][0], b[0][1]);
                MMA16(acc[mt][1], a[mt], b[0][2], b[0][3]);
                MMA16(acc[mt][2], a[mt], b[1][0], b[1][1]);
                MMA16(acc[mt][3], a[mt], b[1][2], b[1][3]);
            }
        }
    }

    const int g = lane >> 2, t = lane & 3;
#pragma unroll
    for (int mt = 0; mt < 4; mt++) {
#pragma unroll
        for (int nt = 0; nt < 4; nt++) {
            int m = mBase + wm + mt*16 + g;
            int n = nBase + wn + nt*8 + 2*t;
#pragma unroll
            for (int half = 0; half < 2; half++) {
                int mm = m + half*8;
                float v0 = half ? acc[mt][nt][2] : acc[mt][nt][0];
                float v1 = half ? acc[mt][nt][3] : acc[mt][nt][1];
                if (MODE == 0) {
                    float* C = (float*)Cv;
                    *(float2*)&C[(size_t)mm * N + n] = make_float2(v0, v1);
                } else {
                    __half* C = (__half*)Cv;
                    int bb = mm >> 10, tk = mm & 1023;
                    int h2 = n >> 7, d = n & 127;
                    int heads = (MODE == 1) ? NH : NKV;
                    __half2 hv = __floats2half2_rn(v0, v1);
                    *(uint32_t*)&C[(((size_t)(bb*heads + h2))*SEQ + tk)*HD + d] = h2_as_u32(hv);
                }
            }
        }
    }
}

// ---------------------------------------------------------------------------
// f32 -> fp16 conversion pre-pass
// ---------------------------------------------------------------------------
__global__ void to_half_kernel(__half* __restrict__ dst, const float* __restrict__ src, int n8)
{
    int i = blockIdx.x * blockDim.x + threadIdx.x;
    if (i < n8) {
        float4 v0 = ((const float4*)src)[2*i];
        float4 v1 = ((const float4*)src)[2*i + 1];
        uint4 o;
        o.x = h2_as_u32(__floats2half2_rn(v0.x, v0.y));
        o.y = h2_as_u32(__floats2half2_rn(v0.z, v0.w));
        o.z = h2_as_u32(__floats2half2_rn(v1.x, v1.y));
        o.w = h2_as_u32(__floats2half2_rn(v1.z, v1.w));
        ((uint4*)dst)[i] = o;
    }
}

// ---------------------------------------------------------------------------
// Tensor-core flash attention (fp16 in, f32 softmax/accum, fp16 out).
// Block: 128 q-rows of one (b,h); 8 warps, 16 rows each. K/V tiles of 64
// keys, 3-stage cp.async. Mask: kpos <= qpos+1 AND id[kpos]!=0; kvh = h%8.
// smem: Q 32KB + 3x16KB K + 3x16KB V + 256B pad bias = 131328 B.
// ---------------------------------------------------------------------------
#define ATTN_SMEM (32768 + 3*16384 + 3*16384 + 256)

__global__ __launch_bounds__(256, 1)
void attn_f16(const int* __restrict__ ids)
{
    extern __shared__ __align__(128) uint8_t smraw[];
    const uint32_t sb = (uint32_t)__cvta_generic_to_shared(smraw);
    const uint32_t Qs = sb;
    const uint32_t Ks = sb + 32768;
    const uint32_t Vs = sb + 32768 + 3*16384;
    float* padb = (float*)(smraw + 32768 + 6*16384);

    const int qt = blockIdx.x, h = blockIdx.y, b = blockIdx.z;
    const int qb  = qt << 7;
    const int kvh = h & 7;
    const int tid = threadIdx.x, w = tid >> 5, lane = tid & 31;
    const int g = lane >> 2, t4 = lane & 3;

    const __half* Qg = g_qh + ((size_t)((b*NH  + h  )*SEQ) + qb) * HD;
    const __half* Kg = g_kh + ((size_t)((b*NKV + kvh)*SEQ)) * HD;
    const __half* Vg = g_vh + ((size_t)((b*NKV + kvh)*SEQ)) * HD;

    // Q tile -> smem (swizzled 256B rows, 16 chunks, XOR row&7)
#pragma unroll
    for (int i = 0; i < 8; i++) {
        int slot = tid + (i << 8);          // 0..2047
        int r = slot >> 4, c = slot & 15;
        cpasync16s(Qs + r*256 + ((c ^ (r & 7)) << 4), Qg + (size_t)r*HD + c*8);
    }
    CP_COMMIT();

    const int limit = min(SEQ, qb + 129);   // keys needed: cols <= row+1
    const int nT = (limit + 63) >> 6;

    auto issueKV = [&](int tt) {
        int st = tt % 3; int k0 = tt << 6;
#pragma unroll
        for (int i = 0; i < 4; i++) {
            int slot = tid + (i << 8);      // 0..1023
            int r = slot >> 4, c = slot & 15;
            uint32_t off = (uint32_t)(r*256 + ((c ^ (r & 7)) << 4));
            cpasync16s(Ks + st*16384 + off, Kg + (size_t)(k0 + r)*HD + c*8);
            cpasync16s(Vs + st*16384 + off, Vg + (size_t)(k0 + r)*HD + c*8);
        }
    };

    issueKV(0); CP_COMMIT();
    if (nT > 1) issueKV(1);
    CP_COMMIT();

    CP_WAIT(2);                 // Q done (tiles 0/1 may still be in flight)
    __syncthreads();

    // Q fragments (register-resident for whole kernel)
    uint32_t qf[8][4];
    const int arow = (w << 4) + (lane & 7) + (((lane >> 3) & 1) << 3);
    const int ahi  = lane >> 4;
#pragma unroll
    for (int kt = 0; kt < 8; kt++) {
        int c = kt*2 + ahi;
        uint32_t ad = Qs + (uint32_t)(arow*256 + ((c ^ (arow & 7)) << 4));
        LDMX4(qf[kt][0], qf[kt][1], qf[kt][2], qf[kt][3], ad);
    }

    const int krow = (lane & 7) + (((lane >> 4) & 1) << 3);
    const int khi  = (lane >> 3) & 1;
    const int vkey = lane & 15;
    const int vhi  = lane >> 4;
    const int row0 = qb + (w << 4) + g;
    const int row1 = row0 + 8;
    const int minrow = qb + (w << 4);

    float m0 = -1e30f, m1 = -1e30f, l0 = 0.f, l1 = 0.f;
    float oacc[16][4];
#pragma unroll
    for (int i = 0; i < 16; i++)
#pragma unroll
        for (int j = 0; j < 4; j++) oacc[i][j] = 0.f;

    for (int tt = 0; tt < nT; tt++) {
        const int st = tt % 3;
        const int k0 = tt << 6;

        __syncthreads();        // prev compute done; padb + stage (tt+2)%3 free
        if (tid < 64) padb[tid] = (ids[b*SEQ + k0 + tid] != 0) ? 0.f : -1e30f;
        if (tt + 2 < nT) issueKV(tt + 2);
        CP_COMMIT();
        CP_WAIT(2);             // tile tt ready
        __syncthreads();

        // ---- S = Q @ K^T  (f32 accum) ----
        float sacc[8][4];
#pragma unroll
        for (int nt = 0; nt < 8; nt++)
#pragma unroll
            for (int j = 0; j < 4; j++) sacc[nt][j] = 0.f;

        const uint32_t KsS = Ks + st*16384;
#pragma unroll
        for (int np = 0; np < 4; np++) {
#pragma unroll
            for (int kt = 0; kt < 8; kt++) {
                int r = np*16 + krow;
                int c = kt*2 + khi;
                uint32_t bd = KsS + (uint32_t)(r*256 + ((c ^ (r & 7)) << 4));
                uint32_t b0, b1, b2, b3;
                LDMX4(b0, b1, b2, b3, bd);
                MMA16(sacc[np*2],     qf[kt], b0, b1);
                MMA16(sacc[np*2 + 1], qf[kt], b2, b3);
            }
        }

        // ---- mask + online softmax ----
        const bool fullc = (k0 + 63 <= minrow + 1);
        const float sc = 0.08838834764831845f;      // 1/sqrt(128)
        float mx0 = -1e30f, mx1 = -1e30f;
        const float2* pb2 = (const float2*)padb;
#pragma unroll
        for (int nt = 0; nt < 8; nt++) {
            float2 pb = pb2[nt*4 + t4];
            float c0 = sacc[nt][0]*sc + pb.x;
            float c1 = sacc[nt][1]*sc + pb.y;
            float c2 = sacc[nt][2]*sc + pb.x;
            float c3 = sacc[nt][3]*sc + pb.y;
            if (!fullc) {
                int col0 = k0 + nt*8 + 2*t4;
                if (col0     > row0 + 1) c0 = -1e30f;
                if (col0 + 1 > row0 + 1) c1 = -1e30f;
                if (col0     > row1 + 1) c2 = -1e30f;
                if (col0 + 1 > row1 + 1) c3 = -1e30f;
            }
            sacc[nt][0] = c0; sacc[nt][1] = c1; sacc[nt][2] = c2; sacc[nt][3] = c3;
            mx0 = fmaxf(mx0, fmaxf(c0, c1));
            mx1 = fmaxf(mx1, fmaxf(c2, c3));
        }
        mx0 = fmaxf(mx0, __shfl_xor_sync(0xffffffffu, mx0, 1));
        mx0 = fmaxf(mx0, __shfl_xor_sync(0xffffffffu, mx0, 2));
        mx1 = fmaxf(mx1, __shfl_xor_sync(0xffffffffu, mx1, 1));
        mx1 = fmaxf(mx1, __shfl_xor_sync(0xffffffffu, mx1, 2));
        float mn0 = fmaxf(m0, mx0), mn1 = fmaxf(m1, mx1);
        float f0 = __expf(m0 - mn0), f1 = __expf(m1 - mn1);
        m0 = mn0; m1 = mn1;

        float s0 = 0.f, s1 = 0.f;
        uint32_t ph[8][2];
#pragma unroll
        for (int nt = 0; nt < 8; nt++) {
            float p0 = __expf(sacc[nt][0] - mn0);
            float p1 = __expf(sacc[nt][1] - mn0);
            float p2 = __expf(sacc[nt][2] - mn1);
            float p3 = __expf(sacc[nt][3] - mn1);
            s0 += p0 + p1; s1 += p2 + p3;
            ph[nt][0] = h2_as_u32(__floats2half2_rn(p0, p1));
            ph[nt][1] = h2_as_u32(__floats2half2_rn(p2, p3));
        }
        s0 += __shfl_xor_sync(0xffffffffu, s0, 1);
        s0 += __shfl_xor_sync(0xffffffffu, s0, 2);
        s1 += __shfl_xor_sync(0xffffffffu, s1, 1);
        s1 += __shfl_xor_sync(0xffffffffu, s1, 2);
        l0 = l0*f0 + s0; l1 = l1*f1 + s1;

#pragma unroll
        for (int nt = 0; nt < 16; nt++) {
            oacc[nt][0] *= f0; oacc[nt][1] *= f0;
            oacc[nt][2] *= f1; oacc[nt][3] *= f1;
        }

        // ---- O += P @ V  (V^T via ldmatrix.trans) ----
        const uint32_t VsS = Vs + st*16384;
#pragma unroll
        for (int kt2 = 0; kt2 < 4; kt2++) {
            uint32_t a[4] = { ph[kt2*2][0], ph[kt2*2][1],
                              ph[kt2*2 + 1][0], ph[kt2*2 + 1][1] };
#pragma unroll
            for (int u = 0; u < 8; u++) {
                int key = kt2*16 + vkey;
                int c = u*2 + vhi;
                uint32_t vd = VsS + (uint32_t)(key*256 + ((c ^ (key & 7)) << 4));
                uint32_t r0, r1, r2, r3;
                LDMX4T(r0, r1, r2, r3, vd);
                MMA16(oacc[u*2],     a, r0, r1);
                MMA16(oacc[u*2 + 1], a, r2, r3);
            }
        }
    }

    // ---- epilogue: normalize, fp16, write to g_oh (b,t, h*128+d) ----
    float i0 = 1.f / l0, i1 = 1.f / l1;
    size_t base0 = ((size_t)b*SEQ + row0)*HID + h*HD;
    size_t base1 = ((size_t)b*SEQ + row1)*HID + h*HD;
#pragma unroll
    for (int nt = 0; nt < 16; nt++) {
        int d = nt*8 + 2*t4;
        __half2 v0 = __floats2half2_rn(oacc[nt][0]*i0, oacc[nt][1]*i0);
        __half2 v1 = __floats2half2_rn(oacc[nt][2]*i1, oacc[nt][3]*i1);
        *(uint32_t*)(g_oh + base0 + d) = h2_as_u32(v0);
        *(uint32_t*)(g_oh + base1 + d) = h2_as_u32(v1);
    }
}

// Tail: reference returns (out, start_pos + Tq) — fill any extra output slots.
__global__ void tail_kernel(float* __restrict__ out, const int* __restrict__ sp, int out_size)
{
    int i = MROWS*HID + blockIdx.x*blockDim.x + threadIdx.x;
    if (i < out_size) {
        int s = sp ? *sp : 0;
        out[i] = (float)(s + SEQ);
    }
}

// ---------------------------------------------------------------------------
extern "C" void kernel_launch(void* const* d_in, const int* in_sizes, int n_in,
                              void* d_out, int out_size)
{
    const int*   ids    = (const int*)  d_in[0];
    const float* hidden = (const float*)d_in[1];
    const float* Wq     = (const float*)d_in[2];
    const float* Wk     = (const float*)d_in[3];
    const float* Wv     = (const float*)d_in[4];
    const float* Wo     = (const float*)d_in[5];
    float*       out    = (float*)d_out;

    __half *qh, *kh, *vh, *oh, *hh, *wqh, *wkh, *wvh, *woh;
    cudaGetSymbolAddress((void**)&qh,  g_qh);
    cudaGetSymbolAddress((void**)&kh,  g_kh);
    cudaGetSymbolAddress((void**)&vh,  g_vh);
    cudaGetSymbolAddress((void**)&oh,  g_oh);
    cudaGetSymbolAddress((void**)&hh,  g_hh);
    cudaGetSymbolAddress((void**)&wqh, g_wqh);
    cudaGetSymbolAddress((void**)&wkh, g_wkh);
    cudaGetSymbolAddress((void**)&wvh, g_wvh);
    cudaGetSymbolAddress((void**)&woh, g_woh);

    cudaFuncSetAttribute(gemm_f16<0>, cudaFuncAttributeMaxDynamicSharedMemorySize, GEMM_SMEM);
    cudaFuncSetAttribute(gemm_f16<1>, cudaFuncAttributeMaxDynamicSharedMemorySize, GEMM_SMEM);
    cudaFuncSetAttribute(gemm_f16<2>, cudaFuncAttributeMaxDynamicSharedMemorySize, GEMM_SMEM);
    cudaFuncSetAttribute(attn_f16,    cudaFuncAttributeMaxDynamicSharedMemorySize, ATTN_SMEM);

    auto conv = [&](__half* d, const float* s, size_t n) {
        int n8 = (int)(n / 8);
        to_half_kernel<<<(n8 + 255)/256, 256>>>(d, s, n8);
    };

    dim3 blk(256);
    conv(hh,  hidden, (size_t)MROWS*HID);                                     // 1
    conv(wqh, Wq,     (size_t)HID*HID);                                       // 2
    conv(wkh, Wk,     (size_t)NKV*HD*HID);                                    // 3
    gemm_f16<1><<<dim3(HID/128,      MROWS/128), blk, GEMM_SMEM>>>(hh, wqh, qh, HID,    HID); // 4
    conv(wvh, Wv,     (size_t)NKV*HD*HID);                                    // 5
    conv(woh, Wo,     (size_t)HID*HID);                                       // 6
    gemm_f16<2><<<dim3((NKV*HD)/128, MROWS/128), blk, GEMM_SMEM>>>(hh, wkh, kh, NKV*HD, HID); // 7
    gemm_f16<2><<<dim3((NKV*HD)/128, MROWS/128), blk, GEMM_SMEM>>>(hh, wvh, vh, NKV*HD, HID); // 8

    attn_f16<<<dim3(SEQ/128, NH, BATCH), blk, ATTN_SMEM>>>(ids);              // 9

    gemm_f16<0><<<dim3(HID/128, MROWS/128), blk, GEMM_SMEM>>>(oh, woh, out, HID, HID); // 10

    if (out_size > MROWS*HID) {
        int rem = out_size - MROWS*HID;
        const int* sp = (n_in > 8) ? (const int*)d_in[8] : nullptr;
        tail_kernel<<<(rem + 127)/128, 128>>>(out, sp, out_size);             // 11
    }
}

// round 12
// speedup vs baseline: 16.6371x; 1.0807x over previous
#include <cuda_runtime.h>
#include <cuda_fp16.h>
#include <cstdint>

#define HID   4096
#define NH    32
#define NKV   8
#define HD    128
#define BATCH 4
#define SEQ   1024
#define MROWS (BATCH*SEQ)   // 4096

// ---------------------------------------------------------------------------
// Scratch (static __device__ — no allocations allowed)
// ---------------------------------------------------------------------------
__device__ __half g_qh [(size_t)BATCH*NH *SEQ*HD];  // (b,h,t,d) fp16
__device__ __half g_kh [(size_t)BATCH*NKV*SEQ*HD];  // (b,kvh,t,d)
__device__ __half g_vh [(size_t)BATCH*NKV*SEQ*HD];
__device__ __half g_oh [(size_t)MROWS*HID];         // attention out fp16
__device__ __half g_hh [(size_t)MROWS*HID];         // hidden fp16
__device__ __half g_wqh[(size_t)HID*HID];
__device__ __half g_wkh[(size_t)NKV*HD*HID];
__device__ __half g_wvh[(size_t)NKV*HD*HID];
__device__ __half g_woh[(size_t)HID*HID];

// ---------------------------------------------------------------------------
__device__ __forceinline__ uint32_t h2_as_u32(__half2 h) {
    uint32_t u; memcpy(&u, &h, 4); return u;
}
__device__ __forceinline__ void cpasync16s(uint32_t s, const void* g) {
    asm volatile("cp.async.cg.shared.global [%0], [%1], 16;" :: "r"(s), "l"(g));
}
#define CP_COMMIT() asm volatile("cp.async.commit_group;")
#define CP_WAIT(n)  asm volatile("cp.async.wait_group %0;" :: "n"(n))

#define LDMX4(r0,r1,r2,r3, addr) \
    asm volatile("ldmatrix.sync.aligned.m8n8.x4.shared.b16 {%0,%1,%2,%3}, [%4];" \
        : "=r"(r0), "=r"(r1), "=r"(r2), "=r"(r3) : "r"(addr))

#define LDMX4T(r0,r1,r2,r3, addr) \
    asm volatile("ldmatrix.sync.aligned.m8n8.x4.trans.shared.b16 {%0,%1,%2,%3}, [%4];" \
        : "=r"(r0), "=r"(r1), "=r"(r2), "=r"(r3) : "r"(addr))

#define MMA16(d, a, b0, b1) \
    asm volatile("mma.sync.aligned.m16n8k16.row.col.f32.f16.f16.f32 " \
        "{%0,%1,%2,%3}, {%4,%5,%6,%7}, {%8,%9}, {%0,%1,%2,%3};" \
        : "+f"((d)[0]), "+f"((d)[1]), "+f"((d)[2]), "+f"((d)[3]) \
        : "r"((a)[0]), "r"((a)[1]), "r"((a)[2]), "r"((a)[3]), "r"(b0), "r"(b1))

// ---------------------------------------------------------------------------
// FP16 mma.sync GEMM:  C = A[M,K] * B[N,K]^T.
// 128x128 CTA tile, BK=64 (128B rows, XOR swizzle c^(r&7)), 3-stage cp.async
// (96KB, 2 CTAs/SM), 8 warps (warp tile 64x32), m16n8k16 via ldmatrix.x4.
// BK=64 halves the per-iteration barrier count vs BK=32 (64 iters vs 128).
// MODE 0: f32 C[m*N+n]; MODE 1: fp16 scatter (b,h,t,d) 32 heads; MODE 2: 8.
// ---------------------------------------------------------------------------
#define STAGE_BYTES (128*128)            // 128 rows * 128B (64 fp16)
#define GEMM_SMEM   (3*2*STAGE_BYTES)    // 96 KB

template<int MODE>
__global__ __launch_bounds__(256, 2)
void gemm_f16(const __half* __restrict__ A, const __half* __restrict__ Bw,
              void* __restrict__ Cv, int N, int K)
{
    extern __shared__ __align__(128) uint8_t sm[];
    const uint32_t sbase = (uint32_t)__cvta_generic_to_shared(sm);
    const uint32_t aB0 = sbase;
    const uint32_t bB0 = sbase + 3*STAGE_BYTES;

    const int tid  = threadIdx.x;
    const int w    = tid >> 5;
    const int lane = tid & 31;
    const int wm   = (w & 1) * 64;
    const int wn   = (w >> 1) * 32;
    const int mBase = blockIdx.y << 7;
    const int nBase = blockIdx.x << 7;
    const __half* Ag = A  + (size_t)mBase * K;
    const __half* Bg = Bw + (size_t)nBase * K;

    // ldmatrix lane geometry (128B rows, swizzle idx = row & 7)
    const int ar  = wm + ((lane >> 3) & 1) * 8 + (lane & 7);
    const int ahi = lane >> 4;
    const int br  = wn + ((lane >> 4) & 1) * 8 + (lane & 7);
    const int bhi = (lane >> 3) & 1;
    const int asw = ar & 7;
    const int bsw = br & 7;

    float acc[4][4][4];
#pragma unroll
    for (int i = 0; i < 4; i++)
#pragma unroll
        for (int j = 0; j < 4; j++)
#pragma unroll
            for (int r = 0; r < 4; r++) acc[i][j][r] = 0.f;

    // cp.async: per stage per array 1024 16B chunks; thread covers 4 each.
    auto issue = [&](int kt) {
        const int st = kt - (kt/3)*3;
        const int k0 = kt << 6;
        const uint32_t aS = aB0 + st*STAGE_BYTES;
        const uint32_t bS = bB0 + st*STAGE_BYTES;
#pragma unroll
        for (int i = 0; i < 4; i++) {
            int slot = tid + (i << 8);
            int r = slot >> 3;           // row 0..127
            int c = slot & 7;            // 16B chunk 0..7
            uint32_t dst = (uint32_t)(r*128 + ((c ^ (r & 7)) << 4));
            cpasync16s(aS + dst, Ag + (size_t)r * K + k0 + c*8);
            cpasync16s(bS + dst, Bg + (size_t)r * K + k0 + c*8);
        }
    };

    const int kTiles = K >> 6;           // K/64
    issue(0); CP_COMMIT();
    issue(1); CP_COMMIT();

    for (int kt = 0; kt < kTiles; kt++) {
        CP_WAIT(1);
        __syncthreads();
        if (kt + 2 < kTiles) issue(kt + 2);
        CP_COMMIT();

        const int st = kt - (kt/3)*3;
        const uint32_t aS = aB0 + st*STAGE_BYTES;
        const uint32_t bS = bB0 + st*STAGE_BYTES;

#pragma unroll
        for (int h = 0; h < 4; h++) {
            uint32_t a[4][4], b[2][4];
#pragma unroll
            for (int mt = 0; mt < 4; mt++) {
                uint32_t ad = aS + (uint32_t)((ar + mt*16)*128
                              + (((2*h + ahi) ^ asw) << 4));
                LDMX4(a[mt][0], a[mt][1], a[mt][2], a[mt][3], ad);
            }
#pragma unroll
            for (int p = 0; p < 2; p++) {
                uint32_t bd = bS + (uint32_t)((br + p*16)*128
                              + (((2*h + bhi) ^ bsw) << 4));
                LDMX4(b[p][0], b[p][1], b[p][2], b[p][3], bd);
            }
#pragma unroll
            for (int mt = 0; mt < 4; mt++) {
                MMA16(acc[mt][0], a[mt], b[0][0], b[0][1]);
                MMA16(acc[mt][1], a[mt], b[0][2], b[0][3]);
                MMA16(acc[mt][2], a[mt], b[1][0], b[1][1]);
                MMA16(acc[mt][3], a[mt], b[1][2], b[1][3]);
            }
        }
    }

    const int g = lane >> 2, t = lane & 3;
#pragma unroll
    for (int mt = 0; mt < 4; mt++) {
#pragma unroll
        for (int nt = 0; nt < 4; nt++) {
            int m = mBase + wm + mt*16 + g;
            int n = nBase + wn + nt*8 + 2*t;
#pragma unroll
            for (int half = 0; half < 2; half++) {
                int mm = m + half*8;
                float v0 = half ? acc[mt][nt][2] : acc[mt][nt][0];
                float v1 = half ? acc[mt][nt][3] : acc[mt][nt][1];
                if (MODE == 0) {
                    float* C = (float*)Cv;
                    *(float2*)&C[(size_t)mm * N + n] = make_float2(v0, v1);
                } else {
                    __half* C = (__half*)Cv;
                    int bb = mm >> 10, tk = mm & 1023;
                    int h2 = n >> 7, d = n & 127;
                    int heads = (MODE == 1) ? NH : NKV;
                    __half2 hv = __floats2half2_rn(v0, v1);
                    *(uint32_t*)&C[(((size_t)(bb*heads + h2))*SEQ + tk)*HD + d] = h2_as_u32(hv);
                }
            }
        }
    }
}

// ---------------------------------------------------------------------------
// f32 -> fp16 conversion pre-pass
// ---------------------------------------------------------------------------
__global__ void to_half_kernel(__half* __restrict__ dst, const float* __restrict__ src, int n8)
{
    int i = blockIdx.x * blockDim.x + threadIdx.x;
    if (i < n8) {
        float4 v0 = ((const float4*)src)[2*i];
        float4 v1 = ((const float4*)src)[2*i + 1];
        uint4 o;
        o.x = h2_as_u32(__floats2half2_rn(v0.x, v0.y));
        o.y = h2_as_u32(__floats2half2_rn(v0.z, v0.w));
        o.z = h2_as_u32(__floats2half2_rn(v1.x, v1.y));
        o.w = h2_as_u32(__floats2half2_rn(v1.z, v1.w));
        ((uint4*)dst)[i] = o;
    }
}

// ---------------------------------------------------------------------------
// Tensor-core flash attention (fp16 in, f32 softmax/accum, fp16 out).
// Block: 128 q-rows of one (b,h); 8 warps, 16 rows each. K/V tiles of 64
// keys, 3-stage cp.async. Mask: kpos <= qpos+1 AND id[kpos]!=0; kvh = h%8.
// ---------------------------------------------------------------------------
#define ATTN_SMEM (32768 + 3*16384 + 3*16384 + 256)

__global__ __launch_bounds__(256, 1)
void attn_f16(const int* __restrict__ ids)
{
    extern __shared__ __align__(128) uint8_t smraw[];
    const uint32_t sb = (uint32_t)__cvta_generic_to_shared(smraw);
    const uint32_t Qs = sb;
    const uint32_t Ks = sb + 32768;
    const uint32_t Vs = sb + 32768 + 3*16384;
    float* padb = (float*)(smraw + 32768 + 6*16384);

    const int qt = blockIdx.x, h = blockIdx.y, b = blockIdx.z;
    const int qb  = qt << 7;
    const int kvh = h & 7;
    const int tid = threadIdx.x, w = tid >> 5, lane = tid & 31;
    const int g = lane >> 2, t4 = lane & 3;

    const __half* Qg = g_qh + ((size_t)((b*NH  + h  )*SEQ) + qb) * HD;
    const __half* Kg = g_kh + ((size_t)((b*NKV + kvh)*SEQ)) * HD;
    const __half* Vg = g_vh + ((size_t)((b*NKV + kvh)*SEQ)) * HD;

#pragma unroll
    for (int i = 0; i < 8; i++) {
        int slot = tid + (i << 8);
        int r = slot >> 4, c = slot & 15;
        cpasync16s(Qs + r*256 + ((c ^ (r & 7)) << 4), Qg + (size_t)r*HD + c*8);
    }
    CP_COMMIT();

    const int limit = min(SEQ, qb + 129);
    const int nT = (limit + 63) >> 6;

    auto issueKV = [&](int tt) {
        int st = tt % 3; int k0 = tt << 6;
#pragma unroll
        for (int i = 0; i < 4; i++) {
            int slot = tid + (i << 8);
            int r = slot >> 4, c = slot & 15;
            uint32_t off = (uint32_t)(r*256 + ((c ^ (r & 7)) << 4));
            cpasync16s(Ks + st*16384 + off, Kg + (size_t)(k0 + r)*HD + c*8);
            cpasync16s(Vs + st*16384 + off, Vg + (size_t)(k0 + r)*HD + c*8);
        }
    };

    issueKV(0); CP_COMMIT();
    if (nT > 1) issueKV(1);
    CP_COMMIT();

    CP_WAIT(2);
    __syncthreads();

    uint32_t qf[8][4];
    const int arow = (w << 4) + (lane & 7) + (((lane >> 3) & 1) << 3);
    const int ahi  = lane >> 4;
#pragma unroll
    for (int kt = 0; kt < 8; kt++) {
        int c = kt*2 + ahi;
        uint32_t ad = Qs + (uint32_t)(arow*256 + ((c ^ (arow & 7)) << 4));
        LDMX4(qf[kt][0], qf[kt][1], qf[kt][2], qf[kt][3], ad);
    }

    const int krow = (lane & 7) + (((lane >> 4) & 1) << 3);
    const int khi  = (lane >> 3) & 1;
    const int vkey = lane & 15;
    const int vhi  = lane >> 4;
    const int row0 = qb + (w << 4) + g;
    const int row1 = row0 + 8;
    const int minrow = qb + (w << 4);

    float m0 = -1e30f, m1 = -1e30f, l0 = 0.f, l1 = 0.f;
    float oacc[16][4];
#pragma unroll
    for (int i = 0; i < 16; i++)
#pragma unroll
        for (int j = 0; j < 4; j++) oacc[i][j] = 0.f;

    for (int tt = 0; tt < nT; tt++) {
        const int st = tt % 3;
        const int k0 = tt << 6;

        __syncthreads();
        if (tid < 64) padb[tid] = (ids[b*SEQ + k0 + tid] != 0) ? 0.f : -1e30f;
        if (tt + 2 < nT) issueKV(tt + 2);
        CP_COMMIT();
        CP_WAIT(2);
        __syncthreads();

        float sacc[8][4];
#pragma unroll
        for (int nt = 0; nt < 8; nt++)
#pragma unroll
            for (int j = 0; j < 4; j++) sacc[nt][j] = 0.f;

        const uint32_t KsS = Ks + st*16384;
#pragma unroll
        for (int np = 0; np < 4; np++) {
#pragma unroll
            for (int kt = 0; kt < 8; kt++) {
                int r = np*16 + krow;
                int c = kt*2 + khi;
                uint32_t bd = KsS + (uint32_t)(r*256 + ((c ^ (r & 7)) << 4));
                uint32_t b0, b1, b2, b3;
                LDMX4(b0, b1, b2, b3, bd);
                MMA16(sacc[np*2],     qf[kt], b0, b1);
                MMA16(sacc[np*2 + 1], qf[kt], b2, b3);
            }
        }

        const bool fullc = (k0 + 63 <= minrow + 1);
        const float sc = 0.08838834764831845f;
        float mx0 = -1e30f, mx1 = -1e30f;
        const float2* pb2 = (const float2*)padb;
#pragma unroll
        for (int nt = 0; nt < 8; nt++) {
            float2 pb = pb2[nt*4 + t4];
            float c0 = sacc[nt][0]*sc + pb.x;
            float c1 = sacc[nt][1]*sc + pb.y;
            float c2 = sacc[nt][2]*sc + pb.x;
            float c3 = sacc[nt][3]*sc + pb.y;
            if (!fullc) {
                int col0 = k0 + nt*8 + 2*t4;
                if (col0     > row0 + 1) c0 = -1e30f;
                if (col0 + 1 > row0 + 1) c1 = -1e30f;
                if (col0     > row1 + 1) c2 = -1e30f;
                if (col0 + 1 > row1 + 1) c3 = -1e30f;
            }
            sacc[nt][0] = c0; sacc[nt][1] = c1; sacc[nt][2] = c2; sacc[nt][3] = c3;
            mx0 = fmaxf(mx0, fmaxf(c0, c1));
            mx1 = fmaxf(mx1, fmaxf(c2, c3));
        }
        mx0 = fmaxf(mx0, __shfl_xor_sync(0xffffffffu, mx0, 1));
        mx0 = fmaxf(mx0, __shfl_xor_sync(0xffffffffu, mx0, 2));
        mx1 = fmaxf(mx1, __shfl_xor_sync(0xffffffffu, mx1, 1));
        mx1 = fmaxf(mx1, __shfl_xor_sync(0xffffffffu, mx1, 2));
        float mn0 = fmaxf(m0, mx0), mn1 = fmaxf(m1, mx1);
        float f0 = __expf(m0 - mn0), f1 = __expf(m1 - mn1);
        m0 = mn0; m1 = mn1;

        float s0 = 0.f, s1 = 0.f;
        uint32_t ph[8][2];
#pragma unroll
        for (int nt = 0; nt < 8; nt++) {
            float p0 = __expf(sacc[nt][0] - mn0);
            float p1 = __expf(sacc[nt][1] - mn0);
            float p2 = __expf(sacc[nt][2] - mn1);
            float p3 = __expf(sacc[nt][3] - mn1);
            s0 += p0 + p1; s1 += p2 + p3;
            ph[nt][0] = h2_as_u32(__floats2half2_rn(p0, p1));
            ph[nt][1] = h2_as_u32(__floats2half2_rn(p2, p3));
        }
        s0 += __shfl_xor_sync(0xffffffffu, s0, 1);
        s0 += __shfl_xor_sync(0xffffffffu, s0, 2);
        s1 += __shfl_xor_sync(0xffffffffu, s1, 1);
        s1 += __shfl_xor_sync(0xffffffffu, s1, 2);
        l0 = l0*f0 + s0; l1 = l1*f1 + s1;

#pragma unroll
        for (int nt = 0; nt < 16; nt++) {
            oacc[nt][0] *= f0; oacc[nt][1] *= f0;
            oacc[nt][2] *= f1; oacc[nt][3] *= f1;
        }

        const uint32_t VsS = Vs + st*16384;
#pragma unroll
        for (int kt2 = 0; kt2 < 4; kt2++) {
            uint32_t a[4] = { ph[kt2*2][0], ph[kt2*2][1],
                              ph[kt2*2 + 1][0], ph[kt2*2 + 1][1] };
#pragma unroll
            for (int u = 0; u < 8; u++) {
                int key = kt2*16 + vkey;
                int c = u*2 + vhi;
                uint32_t vd = VsS + (uint32_t)(key*256 + ((c ^ (key & 7)) << 4));
                uint32_t r0, r1, r2, r3;
                LDMX4T(r0, r1, r2, r3, vd);
                MMA16(oacc[u*2],     a, r0, r1);
                MMA16(oacc[u*2 + 1], a, r2, r3);
            }
        }
    }

    float i0 = 1.f / l0, i1 = 1.f / l1;
    size_t base0 = ((size_t)b*SEQ + row0)*HID + h*HD;
    size_t base1 = ((size_t)b*SEQ + row1)*HID + h*HD;
#pragma unroll
    for (int nt = 0; nt < 16; nt++) {
        int d = nt*8 + 2*t4;
        __half2 v0 = __floats2half2_rn(oacc[nt][0]*i0, oacc[nt][1]*i0);
        __half2 v1 = __floats2half2_rn(oacc[nt][2]*i1, oacc[nt][3]*i1);
        *(uint32_t*)(g_oh + base0 + d) = h2_as_u32(v0);
        *(uint32_t*)(g_oh + base1 + d) = h2_as_u32(v1);
    }
}

// Tail: reference returns (out, start_pos + Tq) — fill any extra output slots.
__global__ void tail_kernel(float* __restrict__ out, const int* __restrict__ sp, int out_size)
{
    int i = MROWS*HID + blockIdx.x*blockDim.x + threadIdx.x;
    if (i < out_size) {
        int s = sp ? *sp : 0;
        out[i] = (float)(s + SEQ);
    }
}

// ---------------------------------------------------------------------------
extern "C" void kernel_launch(void* const* d_in, const int* in_sizes, int n_in,
                              void* d_out, int out_size)
{
    const int*   ids    = (const int*)  d_in[0];
    const float* hidden = (const float*)d_in[1];
    const float* Wq     = (const float*)d_in[2];
    const float* Wk     = (const float*)d_in[3];
    const float* Wv     = (const float*)d_in[4];
    const float* Wo     = (const float*)d_in[5];
    float*       out    = (float*)d_out;

    __half *qh, *kh, *vh, *oh, *hh, *wqh, *wkh, *wvh, *woh;
    cudaGetSymbolAddress((void**)&qh,  g_qh);
    cudaGetSymbolAddress((void**)&kh,  g_kh);
    cudaGetSymbolAddress((void**)&vh,  g_vh);
    cudaGetSymbolAddress((void**)&oh,  g_oh);
    cudaGetSymbolAddress((void**)&hh,  g_hh);
    cudaGetSymbolAddress((void**)&wqh, g_wqh);
    cudaGetSymbolAddress((void**)&wkh, g_wkh);
    cudaGetSymbolAddress((void**)&wvh, g_wvh);
    cudaGetSymbolAddress((void**)&woh, g_woh);

    cudaFuncSetAttribute(gemm_f16<0>, cudaFuncAttributeMaxDynamicSharedMemorySize, GEMM_SMEM);
    cudaFuncSetAttribute(gemm_f16<1>, cudaFuncAttributeMaxDynamicSharedMemorySize, GEMM_SMEM);
    cudaFuncSetAttribute(gemm_f16<2>, cudaFuncAttributeMaxDynamicSharedMemorySize, GEMM_SMEM);
    cudaFuncSetAttribute(attn_f16,    cudaFuncAttributeMaxDynamicSharedMemorySize, ATTN_SMEM);

    auto conv = [&](__half* d, const float* s, size_t n) {
        int n8 = (int)(n / 8);
        to_half_kernel<<<(n8 + 255)/256, 256>>>(d, s, n8);
    };

    dim3 blk(256);
    conv(hh,  hidden, (size_t)MROWS*HID);                                     // 1
    conv(wqh, Wq,     (size_t)HID*HID);                                       // 2
    conv(wkh, Wk,     (size_t)NKV*HD*HID);                                    // 3
    gemm_f16<1><<<dim3(HID/128,      MROWS/128), blk, GEMM_SMEM>>>(hh, wqh, qh, HID,    HID); // 4 <- profiled
    conv(wvh, Wv,     (size_t)NKV*HD*HID);                                    // 5
    conv(woh, Wo,     (size_t)HID*HID);                                       // 6
    gemm_f16<2><<<dim3((NKV*HD)/128, MROWS/128), blk, GEMM_SMEM>>>(hh, wkh, kh, NKV*HD, HID); // 7
    gemm_f16<2><<<dim3((NKV*HD)/128, MROWS/128), blk, GEMM_SMEM>>>(hh, wvh, vh, NKV*HD, HID); // 8

    attn_f16<<<dim3(SEQ/128, NH, BATCH), blk, ATTN_SMEM>>>(ids);              // 9

    gemm_f16<0><<<dim3(HID/128, MROWS/128), blk, GEMM_SMEM>>>(oh, woh, out, HID, HID); // 10

    if (out_size > MROWS*HID) {
        int rem = out_size - MROWS*HID;
        const int* sp = (n_in > 8) ? (const int*)d_in[8] : nullptr;
        tail_kernel<<<(rem + 127)/128, 128>>>(out, sp, out_size);             // 11
    }
}